// round 9
// baseline (speedup 1.0000x reference)
#include <cuda_runtime.h>
#include <cuda_bf16.h>
#include <cstdint>

// ---------------------------------------------------------------------------
// Problem: x (8,2048,1024) -> 16384 tokens x 1024. Expert0 d=512, Expert1 d=256.
// Output: opt (16384*1024 fp32) + recon scalar.
// Strategy: all GEMMs via mma.sync m16n8k16 bf16 (HMMA path; tcgen05 is
// rejected by this harness's compute_100 ptx target) with hi/lo split
// (3-MMA compensation) for fp32-grade accuracy.
// ---------------------------------------------------------------------------
#define TOK   16384
#define HDIM  1024
#define NTOT  (TOK * HDIM)

// ---------------- static scratch (no allocs allowed) -----------------------
__device__ float          g_hs[NTOT];
__device__ __nv_bfloat16  g_hs_hi[NTOT],      g_hs_lo[NTOT];
__device__ __nv_bfloat16  g_h_hi[TOK * 512],  g_h_lo[TOK * 512];
__device__ __nv_bfloat16  g_t_hi[TOK * 256],  g_t_lo[TOK * 256];
__device__ __nv_bfloat16  g_s_hi[TOK * 512],  g_s_lo[TOK * 512];
#define WTOT 2228224
__device__ __nv_bfloat16  g_w_hi[WTOT],       g_w_lo[WTOT];

// ---------------- threefry (exact JAX partitionable PRNG, verified R5) -----
__host__ __device__ __forceinline__ unsigned rotl32_(unsigned x, int r) {
    return (x << r) | (x >> (32 - r));
}
__host__ __device__ __forceinline__ void threefry2x32_(
    unsigned k0, unsigned k1, unsigned x0, unsigned x1,
    unsigned& o0, unsigned& o1)
{
    unsigned ks2 = k0 ^ k1 ^ 0x1BD11BDAu;
    unsigned ks[3] = {k0, k1, ks2};
    x0 += k0; x1 += k1;
    const int RA[4] = {13, 15, 26, 6};
    const int RB[4] = {17, 29, 16, 24};
#pragma unroll
    for (int r = 0; r < 5; ++r) {
        const int* R = (r & 1) ? RB : RA;
#pragma unroll
        for (int j = 0; j < 4; ++j) {
            x0 += x1; x1 = rotl32_(x1, R[j]); x1 ^= x0;
        }
        x0 += ks[(r + 1) % 3];
        x1 += ks[(r + 2) % 3] + (unsigned)(r + 1);
    }
    o0 = x0; o1 = x1;
}
__device__ __forceinline__ float dropout_val(
    float v, unsigned i, unsigned k0, unsigned k1)
{
    unsigned o0, o1;
    threefry2x32_(k0, k1, 0u, i, o0, o1);
    unsigned bits = o0 ^ o1;
    float u = __uint_as_float((bits >> 9) | 0x3f800000u) - 1.0f;
    return (u < 0.8f) ? (v * 1.25f) : 0.0f;
}

__device__ __forceinline__ void split_bf16(float a, __nv_bfloat16& hi, __nv_bfloat16& lo) {
    hi = __float2bfloat16(a);
    lo = __float2bfloat16(a - __bfloat162float(hi));
}

// ---------------- PTX helpers (all plain sm_80-era ISA) --------------------
__device__ __forceinline__ uint32_t smem_u32(const void* p) {
    uint32_t a;
    asm("{ .reg .u64 t; cvta.to.shared.u64 t, %1; cvt.u32.u64 %0, t; }"
        : "=r"(a) : "l"(p));
    return a;
}
__device__ __forceinline__ void cp16(uint32_t s, const void* g) {
    asm volatile("cp.async.cg.shared.global [%0], [%1], 16;"
                 :: "r"(s), "l"(g));
}
__device__ __forceinline__ void cp_commit() {
    asm volatile("cp.async.commit_group;" ::: "memory");
}
template <int N>
__device__ __forceinline__ void cp_wait() {
    asm volatile("cp.async.wait_group %0;" :: "n"(N) : "memory");
}
__device__ __forceinline__ void ldmx4(uint32_t a, uint32_t& r0, uint32_t& r1,
                                      uint32_t& r2, uint32_t& r3) {
    asm volatile("ldmatrix.sync.aligned.m8n8.x4.shared.b16 {%0,%1,%2,%3}, [%4];"
                 : "=r"(r0), "=r"(r1), "=r"(r2), "=r"(r3) : "r"(a));
}
__device__ __forceinline__ void mma16816(float* c, const uint32_t* a,
                                         const uint32_t* b) {
    asm volatile(
        "mma.sync.aligned.m16n8k16.row.col.f32.bf16.bf16.f32 "
        "{%0,%1,%2,%3}, {%4,%5,%6,%7}, {%8,%9}, {%0,%1,%2,%3};"
        : "+f"(c[0]), "+f"(c[1]), "+f"(c[2]), "+f"(c[3])
        : "r"(a[0]), "r"(a[1]), "r"(a[2]), "r"(a[3]), "r"(b[0]), "r"(b[1]));
}

// ---------------------------------------------------------------------------
// Prep: hs = x + 0.002*noise (fp32 + bf16 hi/lo); out init (route==2); recon=0
// ---------------------------------------------------------------------------
__global__ void prep_kernel(const float* __restrict__ x,
                            const float* __restrict__ noise,
                            const int*   __restrict__ route,
                            float* __restrict__ out,
                            float* __restrict__ recon)
{
    unsigned i4 = blockIdx.x * blockDim.x + threadIdx.x;
    unsigned base = i4 * 4u;
    if (base < (unsigned)NTOT) {
        float4 xv = *(const float4*)(x + base);
        float4 nv = *(const float4*)(noise + base);
        float4 h;
        h.x = xv.x + 0.002f * nv.x;
        h.y = xv.y + 0.002f * nv.y;
        h.z = xv.z + 0.002f * nv.z;
        h.w = xv.w + 0.002f * nv.w;
        *(float4*)(g_hs + base) = h;
        __nv_bfloat16 hi[4], lo[4];
        split_bf16(h.x, hi[0], lo[0]);
        split_bf16(h.y, hi[1], lo[1]);
        split_bf16(h.z, hi[2], lo[2]);
        split_bf16(h.w, hi[3], lo[3]);
        *(uint2*)(g_hs_hi + base) = *(uint2*)hi;
        *(uint2*)(g_hs_lo + base) = *(uint2*)lo;
        int s = (int)((base >> 10) & 2047u);
        float4 o = (route[s] == 2) ? h : make_float4(0.f, 0.f, 0.f, 0.f);
        *(float4*)(out + base) = o;
    }
    if (i4 == 0) *recon = 0.0f;
}

// W[K,N] fp32 -> Whi/Wlo[N,K] bf16 (transposed, K-major)
__global__ void wprep_kernel(const float* __restrict__ W,
                             __nv_bfloat16* __restrict__ hi,
                             __nv_bfloat16* __restrict__ lo,
                             int K, int N)
{
    int i = blockIdx.x * 256 + threadIdx.x;
    if (i >= K * N) return;
    int n = i / K, k = i % K;
    float v = W[(size_t)k * N + n];
    __nv_bfloat16 h, l;
    split_bf16(v, h, l);
    hi[i] = h; lo[i] = l;
}

// ---------------------------------------------------------------------------
// HMMA GEMM: C[16384, N] = A[M,K] @ W^T[N,K]^T (+bias), bf16 hi/lo 3-MMA.
// Tile 128x128, BK=32, 8 warps (4m x 2n), warp tile 32x64.
// 2-stage cp.async pipeline. SMEM rows padded to 40 elems (conflict-free
// for both cp.async stores and ldmatrix row patterns).
// ---------------------------------------------------------------------------
#define AS_STRIDE 40
#define TILE_B    (128 * AS_STRIDE * 2)        // 10240 bytes per tile
#define ST_AHI    0
#define ST_ALO    (TILE_B)
#define ST_BHI    (2 * TILE_B)
#define ST_BLO    (3 * TILE_B)
#define STAGE_B   (4 * TILE_B)                 // 40960
#define SMEM_BYTES (2 * STAGE_B)               // 81920

__device__ __forceinline__ void issue_stage(
    uint32_t sb, const __nv_bfloat16* Ahi, const __nv_bfloat16* Alo,
    const __nv_bfloat16* Bhi, const __nv_bfloat16* Blo,
    int brow, int bcol, int K, int k0, int tid)
{
#pragma unroll
    for (int it = 0; it < 2; ++it) {
        int idx = it * 256 + tid;          // 0..511
        int r = idx >> 2, c = idx & 3;
        uint32_t so = (uint32_t)((r * AS_STRIDE + c * 8) * 2);
        size_t ga = (size_t)(brow + r) * K + k0 + c * 8;
        size_t gb = (size_t)(bcol + r) * K + k0 + c * 8;
        cp16(sb + ST_AHI + so, Ahi + ga);
        cp16(sb + ST_ALO + so, Alo + ga);
        cp16(sb + ST_BHI + so, Bhi + gb);
        cp16(sb + ST_BLO + so, Blo + gb);
    }
    cp_commit();
}

template <int EPI>
__global__ void __launch_bounds__(256)
gemm_tc(const __nv_bfloat16* __restrict__ Ahi, const __nv_bfloat16* __restrict__ Alo,
        const __nv_bfloat16* __restrict__ A1hi, const __nv_bfloat16* __restrict__ A1lo,
        const __nv_bfloat16* __restrict__ Bhi, const __nv_bfloat16* __restrict__ Blo,
        const float* __restrict__ bias,
        __nv_bfloat16* __restrict__ Chi, __nv_bfloat16* __restrict__ Clo,
        float* __restrict__ outC,
        int N, int K,
        const int* __restrict__ sub_choice, int expert, int branch_req,
        unsigned key0, unsigned key1,
        const float* __restrict__ hs, const int* __restrict__ route,
        float* __restrict__ recon_out, float recon_scale)
{
    if (branch_req >= 0 && sub_choice[expert] != branch_req) return;
    if (EPI == 2 && sub_choice[expert] < 2) { Ahi = A1hi; Alo = A1lo; }

    extern __shared__ char smem[];
    uint32_t sbase = smem_u32(smem);

    const int tid = threadIdx.x;
    const int wid = tid >> 5, lane = tid & 31;
    const int wm = wid >> 1, wn = wid & 1;      // 4 x 2 warp grid
    const int brow = blockIdx.y * 128, bcol = blockIdx.x * 128;

    float acc[2][8][4];
#pragma unroll
    for (int mi = 0; mi < 2; ++mi)
#pragma unroll
        for (int nj = 0; nj < 8; ++nj)
#pragma unroll
            for (int c = 0; c < 4; ++c) acc[mi][nj][c] = 0.f;

    // ldmatrix source offsets (within a tile), in bytes
    const int a_row = wm * 32 + (lane & 15);            // + mi*16
    const int a_koff = (lane >> 4) * 8;
    const int b_row0 = wn * 64 + (lane & 7) + (lane >> 4) * 8;  // + g*16
    const int b_koff = ((lane >> 3) & 1) * 8;

    const int nch = K >> 5;
    issue_stage(sbase, Ahi, Alo, Bhi, Blo, brow, bcol, K, 0, tid);

    for (int kc = 0; kc < nch; ++kc) {
        if (kc + 1 < nch) {
            issue_stage(sbase + ((kc + 1) & 1) * STAGE_B,
                        Ahi, Alo, Bhi, Blo, brow, bcol, K, (kc + 1) << 5, tid);
            cp_wait<1>();
        } else {
            cp_wait<0>();
        }
        __syncthreads();

        uint32_t st = sbase + (kc & 1) * STAGE_B;
#pragma unroll
        for (int kk = 0; kk < 2; ++kk) {
            int k0s = kk * 16;
            uint32_t ah[2][4], al[2][4];
#pragma unroll
            for (int mi = 0; mi < 2; ++mi) {
                uint32_t ao = (uint32_t)(((a_row + mi * 16) * AS_STRIDE +
                                          k0s + a_koff) * 2);
                ldmx4(st + ST_AHI + ao, ah[mi][0], ah[mi][1], ah[mi][2], ah[mi][3]);
                ldmx4(st + ST_ALO + ao, al[mi][0], al[mi][1], al[mi][2], al[mi][3]);
            }
#pragma unroll
            for (int g = 0; g < 4; ++g) {
                uint32_t bo = (uint32_t)(((b_row0 + g * 16) * AS_STRIDE +
                                          k0s + b_koff) * 2);
                uint32_t bh[4], bl[4];
                ldmx4(st + ST_BHI + bo, bh[0], bh[1], bh[2], bh[3]);
                ldmx4(st + ST_BLO + bo, bl[0], bl[1], bl[2], bl[3]);
#pragma unroll
                for (int p = 0; p < 2; ++p) {
                    int nj = g * 2 + p;
                    uint32_t bfh[2] = {bh[p * 2], bh[p * 2 + 1]};
                    uint32_t bfl[2] = {bl[p * 2], bl[p * 2 + 1]};
#pragma unroll
                    for (int mi = 0; mi < 2; ++mi) {
                        mma16816(acc[mi][nj], ah[mi], bfh);
                        mma16816(acc[mi][nj], ah[mi], bfl);
                        mma16816(acc[mi][nj], al[mi], bfh);
                    }
                }
            }
        }
        __syncthreads();
    }

    // ----------------- epilogue (direct from fragments) -----------------
    const int lane4 = lane >> 2;          // 0..7
    const int lanec = (lane & 3) * 2;
    float lsum = 0.f;

#pragma unroll
    for (int mi = 0; mi < 2; ++mi) {
        int r0g = brow + wm * 32 + mi * 16 + lane4;
        int r1g = r0g + 8;
        int rt0 = 0, rt1 = 0;
        if (EPI == 2) {
            rt0 = route[r0g & 2047];
            rt1 = route[r1g & 2047];
        }
#pragma unroll
        for (int nj = 0; nj < 8; ++nj) {
            int col = bcol + wn * 64 + nj * 8 + lanec;
            float b0 = bias[col], b1 = bias[col + 1];
            float v00 = acc[mi][nj][0] + b0, v01 = acc[mi][nj][1] + b1;
            float v10 = acc[mi][nj][2] + b0, v11 = acc[mi][nj][3] + b1;
            unsigned i0 = (unsigned)r0g * (unsigned)N + (unsigned)col;
            unsigned i1 = (unsigned)r1g * (unsigned)N + (unsigned)col;

            if (EPI == 0 || EPI == 1) {
                v00 = tanhf(v00); v01 = tanhf(v01);
                v10 = tanhf(v10); v11 = tanhf(v11);
                if (EPI == 0) {
                    v00 = dropout_val(v00, i0, key0, key1);
                    v01 = dropout_val(v01, i0 + 1, key0, key1);
                    v10 = dropout_val(v10, i1, key0, key1);
                    v11 = dropout_val(v11, i1 + 1, key0, key1);
                }
                __nv_bfloat16 h0, l0, h1, l1;
                __nv_bfloat162 ph, pl;
                split_bf16(v00, h0, l0); split_bf16(v01, h1, l1);
                ph.x = h0; ph.y = h1; pl.x = l0; pl.y = l1;
                *(__nv_bfloat162*)(Chi + i0) = ph;
                *(__nv_bfloat162*)(Clo + i0) = pl;
                split_bf16(v10, h0, l0); split_bf16(v11, h1, l1);
                ph.x = h0; ph.y = h1; pl.x = l0; pl.y = l1;
                *(__nv_bfloat162*)(Chi + i1) = ph;
                *(__nv_bfloat162*)(Clo + i1) = pl;
            } else {
                float d;
                d = hs[i0] - v00;     lsum += d * d;
                d = hs[i0 + 1] - v01; lsum += d * d;
                d = hs[i1] - v10;     lsum += d * d;
                d = hs[i1 + 1] - v11; lsum += d * d;
                if (rt0 == expert) {
                    outC[i0] = v00; outC[i0 + 1] = v01;
                }
                if (rt1 == expert) {
                    outC[i1] = v10; outC[i1 + 1] = v11;
                }
            }
        }
    }

    if (EPI == 2) {
#pragma unroll
        for (int s = 16; s > 0; s >>= 1)
            lsum += __shfl_xor_sync(0xFFFFFFFFu, lsum, s);
        if (lane == 0) atomicAdd(recon_out, lsum * recon_scale);
    }
}

// ---------------------------------------------------------------------------
// Host side
// ---------------------------------------------------------------------------
extern "C" void kernel_launch(void* const* d_in, const int* in_sizes, int n_in,
                              void* d_out, int out_size)
{
    const float* x          = (const float*)d_in[0];
    const float* noise      = (const float*)d_in[1];
    const int*   route      = (const int*)  d_in[2];
    const int*   sub_choice = (const int*)  d_in[3];

    float* out   = (float*)d_out;
    float* recon = out + (out_size - 1);

    float* p_hs;
    __nv_bfloat16 *p_hs_hi, *p_hs_lo, *p_h_hi, *p_h_lo, *p_t_hi, *p_t_lo,
                  *p_s_hi, *p_s_lo, *p_w_hi, *p_w_lo;
    cudaGetSymbolAddress((void**)&p_hs,    g_hs);
    cudaGetSymbolAddress((void**)&p_hs_hi, g_hs_hi);
    cudaGetSymbolAddress((void**)&p_hs_lo, g_hs_lo);
    cudaGetSymbolAddress((void**)&p_h_hi,  g_h_hi);
    cudaGetSymbolAddress((void**)&p_h_lo,  g_h_lo);
    cudaGetSymbolAddress((void**)&p_t_hi,  g_t_hi);
    cudaGetSymbolAddress((void**)&p_t_lo,  g_t_lo);
    cudaGetSymbolAddress((void**)&p_s_hi,  g_s_hi);
    cudaGetSymbolAddress((void**)&p_s_lo,  g_s_lo);
    cudaGetSymbolAddress((void**)&p_w_hi,  g_w_hi);
    cudaGetSymbolAddress((void**)&p_w_lo,  g_w_lo);

    cudaFuncSetAttribute(gemm_tc<0>, cudaFuncAttributeMaxDynamicSharedMemorySize, SMEM_BYTES);
    cudaFuncSetAttribute(gemm_tc<1>, cudaFuncAttributeMaxDynamicSharedMemorySize, SMEM_BYTES);
    cudaFuncSetAttribute(gemm_tc<2>, cudaFuncAttributeMaxDynamicSharedMemorySize, SMEM_BYTES);

    // --- exact JAX partitionable key derivation (verified R5) ---
    unsigned ek[2][2];
    threefry2x32_(0u, 42u, 0u, 0u, ek[0][0], ek[0][1]);
    threefry2x32_(0u, 42u, 0u, 1u, ek[1][0], ek[1][1]);
    unsigned kk1[2][2], kk2[2][2], kk3[2][2];
    for (int e = 0; e < 2; ++e) {
        threefry2x32_(ek[e][0], ek[e][1], 0u, 0u, kk1[e][0], kk1[e][1]);
        threefry2x32_(ek[e][0], ek[e][1], 0u, 1u, kk2[e][0], kk2[e][1]);
        threefry2x32_(ek[e][0], ek[e][1], 0u, 2u, kk3[e][0], kk3[e][1]);
    }

    prep_kernel<<<NTOT / 4 / 256, 256>>>(x, noise, route, out, recon);

    // --- weight prep: transpose + bf16 split ---
    long woff[2][6];
    {
        long off = 0;
        for (int e = 0; e < 2; ++e) {
            int d = (e == 0) ? 512 : 256, dh = d / 2;
            int Ks[6] = {HDIM, d, dh, d, dh, d};
            int Ns[6] = {d, dh, d, dh, d, HDIM};
            for (int wi = 0; wi < 6; ++wi) {
                woff[e][wi] = off;
                off += (long)Ks[wi] * Ns[wi];
            }
        }
    }
    for (int e = 0; e < 2; ++e) {
        int base = 4 + e * 12;
        int d = (e == 0) ? 512 : 256, dh = d / 2;
        const float* srcs[6] = {
            (const float*)d_in[base + 0],   // dw   [1024, d]
            (const float*)d_in[base + 2],   // s0dw [d, dh]
            (const float*)d_in[base + 4],   // s0uw [dh, d]
            (const float*)d_in[base + 6],   // s1dw [d, dh]
            (const float*)d_in[base + 8],   // s1uw [dh, d]
            (const float*)d_in[base + 10],  // uw   [d, 1024]
        };
        int Ks[6] = {HDIM, d, dh, d, dh, d};
        int Ns[6] = {d, dh, d, dh, d, HDIM};
        for (int wi = 0; wi < 6; ++wi) {
            int tot = Ks[wi] * Ns[wi];
            wprep_kernel<<<(tot + 255) / 256, 256>>>(
                srcs[wi], p_w_hi + woff[e][wi], p_w_lo + woff[e][wi],
                Ks[wi], Ns[wi]);
        }
    }

    const float recon_scale = 1.0f / (2.0f * (float)NTOT);

    for (int e = 0; e < 2; ++e) {
        int base = 4 + e * 12;
        const float* db   = (const float*)d_in[base + 1];
        const float* s0db = (const float*)d_in[base + 3];
        const float* s0ub = (const float*)d_in[base + 5];
        const float* s1db = (const float*)d_in[base + 7];
        const float* s1ub = (const float*)d_in[base + 9];
        const float* ub   = (const float*)d_in[base + 11];
        int d = (e == 0) ? 512 : 256, dh = d / 2;

        // GEMM1: hs @ dw -> tanh -> dropout -> h (bf16 hi/lo)
        gemm_tc<0><<<dim3(d / 128, TOK / 128), 256, SMEM_BYTES>>>(
            p_hs_hi, p_hs_lo, nullptr, nullptr,
            p_w_hi + woff[e][0], p_w_lo + woff[e][0], db,
            p_h_hi, p_h_lo, nullptr,
            d, HDIM, sub_choice, e, -1, kk1[e][0], kk1[e][1],
            nullptr, nullptr, nullptr, 0.f);

        // s0 branch
        gemm_tc<0><<<dim3(dh / 128, TOK / 128), 256, SMEM_BYTES>>>(
            p_h_hi, p_h_lo, nullptr, nullptr,
            p_w_hi + woff[e][1], p_w_lo + woff[e][1], s0db,
            p_t_hi, p_t_lo, nullptr,
            dh, d, sub_choice, e, 0, kk2[e][0], kk2[e][1],
            nullptr, nullptr, nullptr, 0.f);
        gemm_tc<1><<<dim3(d / 128, TOK / 128), 256, SMEM_BYTES>>>(
            p_t_hi, p_t_lo, nullptr, nullptr,
            p_w_hi + woff[e][2], p_w_lo + woff[e][2], s0ub,
            p_s_hi, p_s_lo, nullptr,
            d, dh, sub_choice, e, 0, 0u, 0u,
            nullptr, nullptr, nullptr, 0.f);

        // s1 branch
        gemm_tc<0><<<dim3(dh / 128, TOK / 128), 256, SMEM_BYTES>>>(
            p_h_hi, p_h_lo, nullptr, nullptr,
            p_w_hi + woff[e][3], p_w_lo + woff[e][3], s1db,
            p_t_hi, p_t_lo, nullptr,
            dh, d, sub_choice, e, 1, kk3[e][0], kk3[e][1],
            nullptr, nullptr, nullptr, 0.f);
        gemm_tc<1><<<dim3(d / 128, TOK / 128), 256, SMEM_BYTES>>>(
            p_t_hi, p_t_lo, nullptr, nullptr,
            p_w_hi + woff[e][4], p_w_lo + woff[e][4], s1ub,
            p_s_hi, p_s_lo, nullptr,
            d, dh, sub_choice, e, 1, 0u, 0u,
            nullptr, nullptr, nullptr, 0.f);

        // GEMM3: (choice<2 ? s : h) @ uw -> route-select out + recon
        gemm_tc<2><<<dim3(HDIM / 128, TOK / 128), 256, SMEM_BYTES>>>(
            p_h_hi, p_h_lo, p_s_hi, p_s_lo,
            p_w_hi + woff[e][5], p_w_lo + woff[e][5], ub,
            nullptr, nullptr, out,
            HDIM, d, sub_choice, e, -1, 0u, 0u,
            p_hs, route, recon, recon_scale);
    }
}

// round 10
// speedup vs baseline: 1.1428x; 1.1428x over previous
#include <cuda_runtime.h>
#include <cuda_bf16.h>
#include <cstdint>

// ---------------------------------------------------------------------------
// Problem: x (8,2048,1024) -> 16384 tokens x 1024. Expert0 d=512, Expert1 d=256.
// Output: opt (16384*1024 fp32) + recon scalar.
// Strategy: all GEMMs via mma.sync m16n8k16 bf16 (legacy HMMA; tcgen05 is
// rejected by this harness's compute_100 ptx target) with hi/lo split
// (3-MMA compensation) for fp32-grade accuracy.
// R10: __launch_bounds__(256,2) for 2 CTAs/SM; fused weight-prep kernel.
// ---------------------------------------------------------------------------
#define TOK   16384
#define HDIM  1024
#define NTOT  (TOK * HDIM)

// ---------------- static scratch (no allocs allowed) -----------------------
__device__ float          g_hs[NTOT];
__device__ __nv_bfloat16  g_hs_hi[NTOT],      g_hs_lo[NTOT];
__device__ __nv_bfloat16  g_h_hi[TOK * 512],  g_h_lo[TOK * 512];
__device__ __nv_bfloat16  g_t_hi[TOK * 256],  g_t_lo[TOK * 256];
__device__ __nv_bfloat16  g_s_hi[TOK * 512],  g_s_lo[TOK * 512];
#define WTOT 2228224
__device__ __nv_bfloat16  g_w_hi[WTOT],       g_w_lo[WTOT];

// ---------------- threefry (exact JAX partitionable PRNG, verified R5) -----
__host__ __device__ __forceinline__ unsigned rotl32_(unsigned x, int r) {
    return (x << r) | (x >> (32 - r));
}
__host__ __device__ __forceinline__ void threefry2x32_(
    unsigned k0, unsigned k1, unsigned x0, unsigned x1,
    unsigned& o0, unsigned& o1)
{
    unsigned ks2 = k0 ^ k1 ^ 0x1BD11BDAu;
    unsigned ks[3] = {k0, k1, ks2};
    x0 += k0; x1 += k1;
    const int RA[4] = {13, 15, 26, 6};
    const int RB[4] = {17, 29, 16, 24};
#pragma unroll
    for (int r = 0; r < 5; ++r) {
        const int* R = (r & 1) ? RB : RA;
#pragma unroll
        for (int j = 0; j < 4; ++j) {
            x0 += x1; x1 = rotl32_(x1, R[j]); x1 ^= x0;
        }
        x0 += ks[(r + 1) % 3];
        x1 += ks[(r + 2) % 3] + (unsigned)(r + 1);
    }
    o0 = x0; o1 = x1;
}
__device__ __forceinline__ float dropout_val(
    float v, unsigned i, unsigned k0, unsigned k1)
{
    unsigned o0, o1;
    threefry2x32_(k0, k1, 0u, i, o0, o1);
    unsigned bits = o0 ^ o1;
    float u = __uint_as_float((bits >> 9) | 0x3f800000u) - 1.0f;
    return (u < 0.8f) ? (v * 1.25f) : 0.0f;
}

__device__ __forceinline__ void split_bf16(float a, __nv_bfloat16& hi, __nv_bfloat16& lo) {
    hi = __float2bfloat16(a);
    lo = __float2bfloat16(a - __bfloat162float(hi));
}

// ---------------- PTX helpers (all plain sm_80-era ISA) --------------------
__device__ __forceinline__ uint32_t smem_u32(const void* p) {
    uint32_t a;
    asm("{ .reg .u64 t; cvta.to.shared.u64 t, %1; cvt.u32.u64 %0, t; }"
        : "=r"(a) : "l"(p));
    return a;
}
__device__ __forceinline__ void cp16(uint32_t s, const void* g) {
    asm volatile("cp.async.cg.shared.global [%0], [%1], 16;"
                 :: "r"(s), "l"(g));
}
__device__ __forceinline__ void cp_commit() {
    asm volatile("cp.async.commit_group;" ::: "memory");
}
template <int N>
__device__ __forceinline__ void cp_wait() {
    asm volatile("cp.async.wait_group %0;" :: "n"(N) : "memory");
}
__device__ __forceinline__ void ldmx4(uint32_t a, uint32_t& r0, uint32_t& r1,
                                      uint32_t& r2, uint32_t& r3) {
    asm volatile("ldmatrix.sync.aligned.m8n8.x4.shared.b16 {%0,%1,%2,%3}, [%4];"
                 : "=r"(r0), "=r"(r1), "=r"(r2), "=r"(r3) : "r"(a));
}
__device__ __forceinline__ void mma16816(float* c, const uint32_t* a,
                                         const uint32_t* b) {
    asm volatile(
        "mma.sync.aligned.m16n8k16.row.col.f32.bf16.bf16.f32 "
        "{%0,%1,%2,%3}, {%4,%5,%6,%7}, {%8,%9}, {%0,%1,%2,%3};"
        : "+f"(c[0]), "+f"(c[1]), "+f"(c[2]), "+f"(c[3])
        : "r"(a[0]), "r"(a[1]), "r"(a[2]), "r"(a[3]), "r"(b[0]), "r"(b[1]));
}

// ---------------------------------------------------------------------------
// Prep: hs = x + 0.002*noise (fp32 + bf16 hi/lo); out init (route==2); recon=0
// ---------------------------------------------------------------------------
__global__ void prep_kernel(const float* __restrict__ x,
                            const float* __restrict__ noise,
                            const int*   __restrict__ route,
                            float* __restrict__ out,
                            float* __restrict__ recon)
{
    unsigned i4 = blockIdx.x * blockDim.x + threadIdx.x;
    unsigned base = i4 * 4u;
    if (base < (unsigned)NTOT) {
        float4 xv = *(const float4*)(x + base);
        float4 nv = *(const float4*)(noise + base);
        float4 h;
        h.x = xv.x + 0.002f * nv.x;
        h.y = xv.y + 0.002f * nv.y;
        h.z = xv.z + 0.002f * nv.z;
        h.w = xv.w + 0.002f * nv.w;
        *(float4*)(g_hs + base) = h;
        __nv_bfloat16 hi[4], lo[4];
        split_bf16(h.x, hi[0], lo[0]);
        split_bf16(h.y, hi[1], lo[1]);
        split_bf16(h.z, hi[2], lo[2]);
        split_bf16(h.w, hi[3], lo[3]);
        *(uint2*)(g_hs_hi + base) = *(uint2*)hi;
        *(uint2*)(g_hs_lo + base) = *(uint2*)lo;
        int s = (int)((base >> 10) & 2047u);
        float4 o = (route[s] == 2) ? h : make_float4(0.f, 0.f, 0.f, 0.f);
        *(float4*)(out + base) = o;
    }
    if (i4 == 0) *recon = 0.0f;
}

// ---------------------------------------------------------------------------
// Fused weight prep: all 12 matrices W[K,N] fp32 -> Whi/Wlo[N,K] bf16
// (transposed, K-major) in ONE launch. Segment lookup via prefix sums.
// ---------------------------------------------------------------------------
struct WPrepArgs {
    const float* src[12];
    int K[12];
    int N[12];
    int pref[13];     // element-offset prefix sums (== dest offsets)
};

__global__ void wprep_all(WPrepArgs a,
                          __nv_bfloat16* __restrict__ hi,
                          __nv_bfloat16* __restrict__ lo)
{
    int i = blockIdx.x * 256 + threadIdx.x;
    if (i >= a.pref[12]) return;
    int m = 0;
#pragma unroll
    for (int t = 0; t < 12; ++t)
        if (i >= a.pref[t + 1]) m = t + 1;
    int j = i - a.pref[m];
    int K = a.K[m], N = a.N[m];
    int n = j / K, k = j - n * K;
    float v = a.src[m][(size_t)k * N + n];
    __nv_bfloat16 h, l;
    split_bf16(v, h, l);
    hi[i] = h; lo[i] = l;
}

// ---------------------------------------------------------------------------
// HMMA GEMM: C[16384, N] = A[M,K] @ W[K,N] (+bias), bf16 hi/lo 3-MMA.
// Tile 128x128, BK=32, 8 warps (4m x 2n), warp tile 32x64.
// 2-stage cp.async pipeline; SMEM rows padded to 40 elems.
// __launch_bounds__(256, 2): cap regs at 128 so 2 CTAs/SM co-reside
// (smem 2x80KB = 160KB < 228KB) for cross-CTA latency hiding.
// ---------------------------------------------------------------------------
#define AS_STRIDE 40
#define TILE_B    (128 * AS_STRIDE * 2)        // 10240 bytes per tile
#define ST_AHI    0
#define ST_ALO    (TILE_B)
#define ST_BHI    (2 * TILE_B)
#define ST_BLO    (3 * TILE_B)
#define STAGE_B   (4 * TILE_B)                 // 40960
#define SMEM_BYTES (2 * STAGE_B)               // 81920

__device__ __forceinline__ void issue_stage(
    uint32_t sb, const __nv_bfloat16* Ahi, const __nv_bfloat16* Alo,
    const __nv_bfloat16* Bhi, const __nv_bfloat16* Blo,
    int brow, int bcol, int K, int k0, int tid)
{
#pragma unroll
    for (int it = 0; it < 2; ++it) {
        int idx = it * 256 + tid;          // 0..511
        int r = idx >> 2, c = idx & 3;
        uint32_t so = (uint32_t)((r * AS_STRIDE + c * 8) * 2);
        size_t ga = (size_t)(brow + r) * K + k0 + c * 8;
        size_t gb = (size_t)(bcol + r) * K + k0 + c * 8;
        cp16(sb + ST_AHI + so, Ahi + ga);
        cp16(sb + ST_ALO + so, Alo + ga);
        cp16(sb + ST_BHI + so, Bhi + gb);
        cp16(sb + ST_BLO + so, Blo + gb);
    }
    cp_commit();
}

template <int EPI>
__global__ void __launch_bounds__(256, 2)
gemm_tc(const __nv_bfloat16* __restrict__ Ahi, const __nv_bfloat16* __restrict__ Alo,
        const __nv_bfloat16* __restrict__ A1hi, const __nv_bfloat16* __restrict__ A1lo,
        const __nv_bfloat16* __restrict__ Bhi, const __nv_bfloat16* __restrict__ Blo,
        const float* __restrict__ bias,
        __nv_bfloat16* __restrict__ Chi, __nv_bfloat16* __restrict__ Clo,
        float* __restrict__ outC,
        int N, int K,
        const int* __restrict__ sub_choice, int expert, int branch_req,
        unsigned key0, unsigned key1,
        const float* __restrict__ hs, const int* __restrict__ route,
        float* __restrict__ recon_out, float recon_scale)
{
    if (branch_req >= 0 && sub_choice[expert] != branch_req) return;
    if (EPI == 2 && sub_choice[expert] < 2) { Ahi = A1hi; Alo = A1lo; }

    extern __shared__ char smem[];
    uint32_t sbase = smem_u32(smem);

    const int tid = threadIdx.x;
    const int wid = tid >> 5, lane = tid & 31;
    const int wm = wid >> 1, wn = wid & 1;      // 4 x 2 warp grid
    const int brow = blockIdx.y * 128, bcol = blockIdx.x * 128;

    float acc[2][8][4];
#pragma unroll
    for (int mi = 0; mi < 2; ++mi)
#pragma unroll
        for (int nj = 0; nj < 8; ++nj)
#pragma unroll
            for (int c = 0; c < 4; ++c) acc[mi][nj][c] = 0.f;

    // ldmatrix source offsets (within a tile), in elements
    const int a_row = wm * 32 + (lane & 15);            // + mi*16
    const int a_koff = (lane >> 4) * 8;
    const int b_row0 = wn * 64 + (lane & 7) + (lane >> 4) * 8;  // + g*16
    const int b_koff = ((lane >> 3) & 1) * 8;

    const int nch = K >> 5;
    issue_stage(sbase, Ahi, Alo, Bhi, Blo, brow, bcol, K, 0, tid);

    for (int kc = 0; kc < nch; ++kc) {
        if (kc + 1 < nch) {
            issue_stage(sbase + ((kc + 1) & 1) * STAGE_B,
                        Ahi, Alo, Bhi, Blo, brow, bcol, K, (kc + 1) << 5, tid);
            cp_wait<1>();
        } else {
            cp_wait<0>();
        }
        __syncthreads();

        uint32_t st = sbase + (kc & 1) * STAGE_B;
#pragma unroll
        for (int kk = 0; kk < 2; ++kk) {
            int k0s = kk * 16;
            uint32_t ah[2][4], al[2][4];
#pragma unroll
            for (int mi = 0; mi < 2; ++mi) {
                uint32_t ao = (uint32_t)(((a_row + mi * 16) * AS_STRIDE +
                                          k0s + a_koff) * 2);
                ldmx4(st + ST_AHI + ao, ah[mi][0], ah[mi][1], ah[mi][2], ah[mi][3]);
                ldmx4(st + ST_ALO + ao, al[mi][0], al[mi][1], al[mi][2], al[mi][3]);
            }
#pragma unroll
            for (int g = 0; g < 4; ++g) {
                uint32_t bo = (uint32_t)(((b_row0 + g * 16) * AS_STRIDE +
                                          k0s + b_koff) * 2);
                uint32_t bh[4], bl[4];
                ldmx4(st + ST_BHI + bo, bh[0], bh[1], bh[2], bh[3]);
                ldmx4(st + ST_BLO + bo, bl[0], bl[1], bl[2], bl[3]);
#pragma unroll
                for (int p = 0; p < 2; ++p) {
                    int nj = g * 2 + p;
                    uint32_t bfh[2] = {bh[p * 2], bh[p * 2 + 1]};
                    uint32_t bfl[2] = {bl[p * 2], bl[p * 2 + 1]};
#pragma unroll
                    for (int mi = 0; mi < 2; ++mi) {
                        mma16816(acc[mi][nj], ah[mi], bfh);
                        mma16816(acc[mi][nj], ah[mi], bfl);
                        mma16816(acc[mi][nj], al[mi], bfh);
                    }
                }
            }
        }
        __syncthreads();
    }

    // ----------------- epilogue (direct from fragments) -----------------
    const int lane4 = lane >> 2;          // 0..7
    const int lanec = (lane & 3) * 2;
    float lsum = 0.f;

#pragma unroll
    for (int mi = 0; mi < 2; ++mi) {
        int r0g = brow + wm * 32 + mi * 16 + lane4;
        int r1g = r0g + 8;
        int rt0 = 0, rt1 = 0;
        if (EPI == 2) {
            rt0 = route[r0g & 2047];
            rt1 = route[r1g & 2047];
        }
#pragma unroll
        for (int nj = 0; nj < 8; ++nj) {
            int col = bcol + wn * 64 + nj * 8 + lanec;
            float b0 = bias[col], b1 = bias[col + 1];
            float v00 = acc[mi][nj][0] + b0, v01 = acc[mi][nj][1] + b1;
            float v10 = acc[mi][nj][2] + b0, v11 = acc[mi][nj][3] + b1;
            unsigned i0 = (unsigned)r0g * (unsigned)N + (unsigned)col;
            unsigned i1 = (unsigned)r1g * (unsigned)N + (unsigned)col;

            if (EPI == 0 || EPI == 1) {
                v00 = tanhf(v00); v01 = tanhf(v01);
                v10 = tanhf(v10); v11 = tanhf(v11);
                if (EPI == 0) {
                    v00 = dropout_val(v00, i0, key0, key1);
                    v01 = dropout_val(v01, i0 + 1, key0, key1);
                    v10 = dropout_val(v10, i1, key0, key1);
                    v11 = dropout_val(v11, i1 + 1, key0, key1);
                }
                __nv_bfloat16 h0, l0, h1, l1;
                __nv_bfloat162 ph, pl;
                split_bf16(v00, h0, l0); split_bf16(v01, h1, l1);
                ph.x = h0; ph.y = h1; pl.x = l0; pl.y = l1;
                *(__nv_bfloat162*)(Chi + i0) = ph;
                *(__nv_bfloat162*)(Clo + i0) = pl;
                split_bf16(v10, h0, l0); split_bf16(v11, h1, l1);
                ph.x = h0; ph.y = h1; pl.x = l0; pl.y = l1;
                *(__nv_bfloat162*)(Chi + i1) = ph;
                *(__nv_bfloat162*)(Clo + i1) = pl;
            } else {
                float d;
                d = hs[i0] - v00;     lsum += d * d;
                d = hs[i0 + 1] - v01; lsum += d * d;
                d = hs[i1] - v10;     lsum += d * d;
                d = hs[i1 + 1] - v11; lsum += d * d;
                if (rt0 == expert) {
                    outC[i0] = v00; outC[i0 + 1] = v01;
                }
                if (rt1 == expert) {
                    outC[i1] = v10; outC[i1 + 1] = v11;
                }
            }
        }
    }

    if (EPI == 2) {
#pragma unroll
        for (int s = 16; s > 0; s >>= 1)
            lsum += __shfl_xor_sync(0xFFFFFFFFu, lsum, s);
        if (lane == 0) atomicAdd(recon_out, lsum * recon_scale);
    }
}

// ---------------------------------------------------------------------------
// Host side
// ---------------------------------------------------------------------------
extern "C" void kernel_launch(void* const* d_in, const int* in_sizes, int n_in,
                              void* d_out, int out_size)
{
    const float* x          = (const float*)d_in[0];
    const float* noise      = (const float*)d_in[1];
    const int*   route      = (const int*)  d_in[2];
    const int*   sub_choice = (const int*)  d_in[3];

    float* out   = (float*)d_out;
    float* recon = out + (out_size - 1);

    float* p_hs;
    __nv_bfloat16 *p_hs_hi, *p_hs_lo, *p_h_hi, *p_h_lo, *p_t_hi, *p_t_lo,
                  *p_s_hi, *p_s_lo, *p_w_hi, *p_w_lo;
    cudaGetSymbolAddress((void**)&p_hs,    g_hs);
    cudaGetSymbolAddress((void**)&p_hs_hi, g_hs_hi);
    cudaGetSymbolAddress((void**)&p_hs_lo, g_hs_lo);
    cudaGetSymbolAddress((void**)&p_h_hi,  g_h_hi);
    cudaGetSymbolAddress((void**)&p_h_lo,  g_h_lo);
    cudaGetSymbolAddress((void**)&p_t_hi,  g_t_hi);
    cudaGetSymbolAddress((void**)&p_t_lo,  g_t_lo);
    cudaGetSymbolAddress((void**)&p_s_hi,  g_s_hi);
    cudaGetSymbolAddress((void**)&p_s_lo,  g_s_lo);
    cudaGetSymbolAddress((void**)&p_w_hi,  g_w_hi);
    cudaGetSymbolAddress((void**)&p_w_lo,  g_w_lo);

    cudaFuncSetAttribute(gemm_tc<0>, cudaFuncAttributeMaxDynamicSharedMemorySize, SMEM_BYTES);
    cudaFuncSetAttribute(gemm_tc<1>, cudaFuncAttributeMaxDynamicSharedMemorySize, SMEM_BYTES);
    cudaFuncSetAttribute(gemm_tc<2>, cudaFuncAttributeMaxDynamicSharedMemorySize, SMEM_BYTES);

    // --- exact JAX partitionable key derivation (verified R5) ---
    unsigned ek[2][2];
    threefry2x32_(0u, 42u, 0u, 0u, ek[0][0], ek[0][1]);
    threefry2x32_(0u, 42u, 0u, 1u, ek[1][0], ek[1][1]);
    unsigned kk1[2][2], kk2[2][2], kk3[2][2];
    for (int e = 0; e < 2; ++e) {
        threefry2x32_(ek[e][0], ek[e][1], 0u, 0u, kk1[e][0], kk1[e][1]);
        threefry2x32_(ek[e][0], ek[e][1], 0u, 1u, kk2[e][0], kk2[e][1]);
        threefry2x32_(ek[e][0], ek[e][1], 0u, 2u, kk3[e][0], kk3[e][1]);
    }

    prep_kernel<<<NTOT / 4 / 256, 256>>>(x, noise, route, out, recon);

    // --- fused weight prep: 12 matrices, one launch ---
    long woff[2][6];
    WPrepArgs wa;
    {
        int off = 0, m = 0;
        for (int e = 0; e < 2; ++e) {
            int base = 4 + e * 12;
            int d = (e == 0) ? 512 : 256, dh = d / 2;
            const float* srcs[6] = {
                (const float*)d_in[base + 0],   // dw   [1024, d]
                (const float*)d_in[base + 2],   // s0dw [d, dh]
                (const float*)d_in[base + 4],   // s0uw [dh, d]
                (const float*)d_in[base + 6],   // s1dw [d, dh]
                (const float*)d_in[base + 8],   // s1uw [dh, d]
                (const float*)d_in[base + 10],  // uw   [d, 1024]
            };
            int Ks[6] = {HDIM, d, dh, d, dh, d};
            int Ns[6] = {d, dh, d, dh, d, HDIM};
            for (int wi = 0; wi < 6; ++wi, ++m) {
                woff[e][wi] = off;
                wa.src[m] = srcs[wi];
                wa.K[m] = Ks[wi];
                wa.N[m] = Ns[wi];
                wa.pref[m] = off;
                off += Ks[wi] * Ns[wi];
            }
        }
        wa.pref[12] = off;
        wprep_all<<<(off + 255) / 256, 256>>>(wa, p_w_hi, p_w_lo);
    }

    const float recon_scale = 1.0f / (2.0f * (float)NTOT);

    for (int e = 0; e < 2; ++e) {
        int base = 4 + e * 12;
        const float* db   = (const float*)d_in[base + 1];
        const float* s0db = (const float*)d_in[base + 3];
        const float* s0ub = (const float*)d_in[base + 5];
        const float* s1db = (const float*)d_in[base + 7];
        const float* s1ub = (const float*)d_in[base + 9];
        const float* ub   = (const float*)d_in[base + 11];
        int d = (e == 0) ? 512 : 256, dh = d / 2;

        // GEMM1: hs @ dw -> tanh -> dropout -> h (bf16 hi/lo)
        gemm_tc<0><<<dim3(d / 128, TOK / 128), 256, SMEM_BYTES>>>(
            p_hs_hi, p_hs_lo, nullptr, nullptr,
            p_w_hi + woff[e][0], p_w_lo + woff[e][0], db,
            p_h_hi, p_h_lo, nullptr,
            d, HDIM, sub_choice, e, -1, kk1[e][0], kk1[e][1],
            nullptr, nullptr, nullptr, 0.f);

        // s0 branch
        gemm_tc<0><<<dim3(dh / 128, TOK / 128), 256, SMEM_BYTES>>>(
            p_h_hi, p_h_lo, nullptr, nullptr,
            p_w_hi + woff[e][1], p_w_lo + woff[e][1], s0db,
            p_t_hi, p_t_lo, nullptr,
            dh, d, sub_choice, e, 0, kk2[e][0], kk2[e][1],
            nullptr, nullptr, nullptr, 0.f);
        gemm_tc<1><<<dim3(d / 128, TOK / 128), 256, SMEM_BYTES>>>(
            p_t_hi, p_t_lo, nullptr, nullptr,
            p_w_hi + woff[e][2], p_w_lo + woff[e][2], s0ub,
            p_s_hi, p_s_lo, nullptr,
            d, dh, sub_choice, e, 0, 0u, 0u,
            nullptr, nullptr, nullptr, 0.f);

        // s1 branch
        gemm_tc<0><<<dim3(dh / 128, TOK / 128), 256, SMEM_BYTES>>>(
            p_h_hi, p_h_lo, nullptr, nullptr,
            p_w_hi + woff[e][3], p_w_lo + woff[e][3], s1db,
            p_t_hi, p_t_lo, nullptr,
            dh, d, sub_choice, e, 1, kk3[e][0], kk3[e][1],
            nullptr, nullptr, nullptr, 0.f);
        gemm_tc<1><<<dim3(d / 128, TOK / 128), 256, SMEM_BYTES>>>(
            p_t_hi, p_t_lo, nullptr, nullptr,
            p_w_hi + woff[e][4], p_w_lo + woff[e][4], s1ub,
            p_s_hi, p_s_lo, nullptr,
            d, dh, sub_choice, e, 1, 0u, 0u,
            nullptr, nullptr, nullptr, 0.f);

        // GEMM3: (choice<2 ? s : h) @ uw -> route-select out + recon
        gemm_tc<2><<<dim3(HDIM / 128, TOK / 128), 256, SMEM_BYTES>>>(
            p_h_hi, p_h_lo, p_s_hi, p_s_lo,
            p_w_hi + woff[e][5], p_w_lo + woff[e][5], ub,
            nullptr, nullptr, out,
            HDIM, d, sub_choice, e, -1, 0u, 0u,
            p_hs, route, recon, recon_scale);
    }
}

// round 11
// speedup vs baseline: 1.2922x; 1.1307x over previous
#include <cuda_runtime.h>
#include <cuda_bf16.h>
#include <cstdint>

// ---------------------------------------------------------------------------
// Problem: x (8,2048,1024) -> 16384 tokens x 1024. Expert0 d=512, Expert1 d=256.
// Output: opt (16384*1024 fp32) + recon scalar.
// Strategy: all GEMMs via mma.sync m16n8k16 bf16 (legacy HMMA; tcgen05 is
// rejected by this harness's compute_100 ptx target) with hi/lo split
// (3-MMA compensation) for fp32-grade accuracy.
// R11: the two expert chains run on parallel streams (graph fork/join) with
// per-expert activation buffers -> fills wave-quantization bubbles.
// ---------------------------------------------------------------------------
#define TOK   16384
#define HDIM  1024
#define NTOT  (TOK * HDIM)

// ---------------- static scratch (no allocs allowed) -----------------------
__device__ float          g_hs[NTOT];
__device__ __nv_bfloat16  g_hs_hi[NTOT],          g_hs_lo[NTOT];
__device__ __nv_bfloat16  g_h_hi[2 * TOK * 512],  g_h_lo[2 * TOK * 512];
__device__ __nv_bfloat16  g_t_hi[2 * TOK * 256],  g_t_lo[2 * TOK * 256];
__device__ __nv_bfloat16  g_s_hi[2 * TOK * 512],  g_s_lo[2 * TOK * 512];
#define WTOT 2228224
__device__ __nv_bfloat16  g_w_hi[WTOT],           g_w_lo[WTOT];

// ---------------- threefry (exact JAX partitionable PRNG, verified R5) -----
__host__ __device__ __forceinline__ unsigned rotl32_(unsigned x, int r) {
    return (x << r) | (x >> (32 - r));
}
__host__ __device__ __forceinline__ void threefry2x32_(
    unsigned k0, unsigned k1, unsigned x0, unsigned x1,
    unsigned& o0, unsigned& o1)
{
    unsigned ks2 = k0 ^ k1 ^ 0x1BD11BDAu;
    unsigned ks[3] = {k0, k1, ks2};
    x0 += k0; x1 += k1;
    const int RA[4] = {13, 15, 26, 6};
    const int RB[4] = {17, 29, 16, 24};
#pragma unroll
    for (int r = 0; r < 5; ++r) {
        const int* R = (r & 1) ? RB : RA;
#pragma unroll
        for (int j = 0; j < 4; ++j) {
            x0 += x1; x1 = rotl32_(x1, R[j]); x1 ^= x0;
        }
        x0 += ks[(r + 1) % 3];
        x1 += ks[(r + 2) % 3] + (unsigned)(r + 1);
    }
    o0 = x0; o1 = x1;
}
__device__ __forceinline__ float dropout_val(
    float v, unsigned i, unsigned k0, unsigned k1)
{
    unsigned o0, o1;
    threefry2x32_(k0, k1, 0u, i, o0, o1);
    unsigned bits = o0 ^ o1;
    float u = __uint_as_float((bits >> 9) | 0x3f800000u) - 1.0f;
    return (u < 0.8f) ? (v * 1.25f) : 0.0f;
}

__device__ __forceinline__ void split_bf16(float a, __nv_bfloat16& hi, __nv_bfloat16& lo) {
    hi = __float2bfloat16(a);
    lo = __float2bfloat16(a - __bfloat162float(hi));
}

// ---------------- PTX helpers (all plain sm_80-era ISA) --------------------
__device__ __forceinline__ uint32_t smem_u32(const void* p) {
    uint32_t a;
    asm("{ .reg .u64 t; cvta.to.shared.u64 t, %1; cvt.u32.u64 %0, t; }"
        : "=r"(a) : "l"(p));
    return a;
}
__device__ __forceinline__ void cp16(uint32_t s, const void* g) {
    asm volatile("cp.async.cg.shared.global [%0], [%1], 16;"
                 :: "r"(s), "l"(g));
}
__device__ __forceinline__ void cp_commit() {
    asm volatile("cp.async.commit_group;" ::: "memory");
}
template <int N>
__device__ __forceinline__ void cp_wait() {
    asm volatile("cp.async.wait_group %0;" :: "n"(N) : "memory");
}
__device__ __forceinline__ void ldmx4(uint32_t a, uint32_t& r0, uint32_t& r1,
                                      uint32_t& r2, uint32_t& r3) {
    asm volatile("ldmatrix.sync.aligned.m8n8.x4.shared.b16 {%0,%1,%2,%3}, [%4];"
                 : "=r"(r0), "=r"(r1), "=r"(r2), "=r"(r3) : "r"(a));
}
__device__ __forceinline__ void mma16816(float* c, const uint32_t* a,
                                         const uint32_t* b) {
    asm volatile(
        "mma.sync.aligned.m16n8k16.row.col.f32.bf16.bf16.f32 "
        "{%0,%1,%2,%3}, {%4,%5,%6,%7}, {%8,%9}, {%0,%1,%2,%3};"
        : "+f"(c[0]), "+f"(c[1]), "+f"(c[2]), "+f"(c[3])
        : "r"(a[0]), "r"(a[1]), "r"(a[2]), "r"(a[3]), "r"(b[0]), "r"(b[1]));
}

// ---------------------------------------------------------------------------
// Prep: hs = x + 0.002*noise (fp32 + bf16 hi/lo); out init (route==2); recon=0
// ---------------------------------------------------------------------------
__global__ void prep_kernel(const float* __restrict__ x,
                            const float* __restrict__ noise,
                            const int*   __restrict__ route,
                            float* __restrict__ out,
                            float* __restrict__ recon)
{
    unsigned i4 = blockIdx.x * blockDim.x + threadIdx.x;
    unsigned base = i4 * 4u;
    if (base < (unsigned)NTOT) {
        float4 xv = *(const float4*)(x + base);
        float4 nv = *(const float4*)(noise + base);
        float4 h;
        h.x = xv.x + 0.002f * nv.x;
        h.y = xv.y + 0.002f * nv.y;
        h.z = xv.z + 0.002f * nv.z;
        h.w = xv.w + 0.002f * nv.w;
        *(float4*)(g_hs + base) = h;
        __nv_bfloat16 hi[4], lo[4];
        split_bf16(h.x, hi[0], lo[0]);
        split_bf16(h.y, hi[1], lo[1]);
        split_bf16(h.z, hi[2], lo[2]);
        split_bf16(h.w, hi[3], lo[3]);
        *(uint2*)(g_hs_hi + base) = *(uint2*)hi;
        *(uint2*)(g_hs_lo + base) = *(uint2*)lo;
        int s = (int)((base >> 10) & 2047u);
        float4 o = (route[s] == 2) ? h : make_float4(0.f, 0.f, 0.f, 0.f);
        *(float4*)(out + base) = o;
    }
    if (i4 == 0) *recon = 0.0f;
}

// ---------------------------------------------------------------------------
// Fused weight prep: all 12 matrices W[K,N] fp32 -> Whi/Wlo[N,K] bf16
// (transposed, K-major) in ONE launch. Segment lookup via prefix sums.
// ---------------------------------------------------------------------------
struct WPrepArgs {
    const float* src[12];
    int K[12];
    int N[12];
    int pref[13];
};

__global__ void wprep_all(WPrepArgs a,
                          __nv_bfloat16* __restrict__ hi,
                          __nv_bfloat16* __restrict__ lo)
{
    int i = blockIdx.x * 256 + threadIdx.x;
    if (i >= a.pref[12]) return;
    int m = 0;
#pragma unroll
    for (int t = 0; t < 12; ++t)
        if (i >= a.pref[t + 1]) m = t + 1;
    int j = i - a.pref[m];
    int K = a.K[m], N = a.N[m];
    int n = j / K, k = j - n * K;
    float v = a.src[m][(size_t)k * N + n];
    __nv_bfloat16 h, l;
    split_bf16(v, h, l);
    hi[i] = h; lo[i] = l;
}

// ---------------------------------------------------------------------------
// HMMA GEMM (unchanged from R10): tile 128x128, BK=32, 8 warps, 2-stage
// cp.async pipeline, bf16 hi/lo 3-MMA. __launch_bounds__(256,2).
// ---------------------------------------------------------------------------
#define AS_STRIDE 40
#define TILE_B    (128 * AS_STRIDE * 2)
#define ST_AHI    0
#define ST_ALO    (TILE_B)
#define ST_BHI    (2 * TILE_B)
#define ST_BLO    (3 * TILE_B)
#define STAGE_B   (4 * TILE_B)
#define SMEM_BYTES (2 * STAGE_B)

__device__ __forceinline__ void issue_stage(
    uint32_t sb, const __nv_bfloat16* Ahi, const __nv_bfloat16* Alo,
    const __nv_bfloat16* Bhi, const __nv_bfloat16* Blo,
    int brow, int bcol, int K, int k0, int tid)
{
#pragma unroll
    for (int it = 0; it < 2; ++it) {
        int idx = it * 256 + tid;
        int r = idx >> 2, c = idx & 3;
        uint32_t so = (uint32_t)((r * AS_STRIDE + c * 8) * 2);
        size_t ga = (size_t)(brow + r) * K + k0 + c * 8;
        size_t gb = (size_t)(bcol + r) * K + k0 + c * 8;
        cp16(sb + ST_AHI + so, Ahi + ga);
        cp16(sb + ST_ALO + so, Alo + ga);
        cp16(sb + ST_BHI + so, Bhi + gb);
        cp16(sb + ST_BLO + so, Blo + gb);
    }
    cp_commit();
}

template <int EPI>
__global__ void __launch_bounds__(256, 2)
gemm_tc(const __nv_bfloat16* __restrict__ Ahi, const __nv_bfloat16* __restrict__ Alo,
        const __nv_bfloat16* __restrict__ A1hi, const __nv_bfloat16* __restrict__ A1lo,
        const __nv_bfloat16* __restrict__ Bhi, const __nv_bfloat16* __restrict__ Blo,
        const float* __restrict__ bias,
        __nv_bfloat16* __restrict__ Chi, __nv_bfloat16* __restrict__ Clo,
        float* __restrict__ outC,
        int N, int K,
        const int* __restrict__ sub_choice, int expert, int branch_req,
        unsigned key0, unsigned key1,
        const float* __restrict__ hs, const int* __restrict__ route,
        float* __restrict__ recon_out, float recon_scale)
{
    if (branch_req >= 0 && sub_choice[expert] != branch_req) return;
    if (EPI == 2 && sub_choice[expert] < 2) { Ahi = A1hi; Alo = A1lo; }

    extern __shared__ char smem[];
    uint32_t sbase = smem_u32(smem);

    const int tid = threadIdx.x;
    const int wid = tid >> 5, lane = tid & 31;
    const int wm = wid >> 1, wn = wid & 1;
    const int brow = blockIdx.y * 128, bcol = blockIdx.x * 128;

    float acc[2][8][4];
#pragma unroll
    for (int mi = 0; mi < 2; ++mi)
#pragma unroll
        for (int nj = 0; nj < 8; ++nj)
#pragma unroll
            for (int c = 0; c < 4; ++c) acc[mi][nj][c] = 0.f;

    const int a_row = wm * 32 + (lane & 15);
    const int a_koff = (lane >> 4) * 8;
    const int b_row0 = wn * 64 + (lane & 7) + (lane >> 4) * 8;
    const int b_koff = ((lane >> 3) & 1) * 8;

    const int nch = K >> 5;
    issue_stage(sbase, Ahi, Alo, Bhi, Blo, brow, bcol, K, 0, tid);

    for (int kc = 0; kc < nch; ++kc) {
        if (kc + 1 < nch) {
            issue_stage(sbase + ((kc + 1) & 1) * STAGE_B,
                        Ahi, Alo, Bhi, Blo, brow, bcol, K, (kc + 1) << 5, tid);
            cp_wait<1>();
        } else {
            cp_wait<0>();
        }
        __syncthreads();

        uint32_t st = sbase + (kc & 1) * STAGE_B;
#pragma unroll
        for (int kk = 0; kk < 2; ++kk) {
            int k0s = kk * 16;
            uint32_t ah[2][4], al[2][4];
#pragma unroll
            for (int mi = 0; mi < 2; ++mi) {
                uint32_t ao = (uint32_t)(((a_row + mi * 16) * AS_STRIDE +
                                          k0s + a_koff) * 2);
                ldmx4(st + ST_AHI + ao, ah[mi][0], ah[mi][1], ah[mi][2], ah[mi][3]);
                ldmx4(st + ST_ALO + ao, al[mi][0], al[mi][1], al[mi][2], al[mi][3]);
            }
#pragma unroll
            for (int g = 0; g < 4; ++g) {
                uint32_t bo = (uint32_t)(((b_row0 + g * 16) * AS_STRIDE +
                                          k0s + b_koff) * 2);
                uint32_t bh[4], bl[4];
                ldmx4(st + ST_BHI + bo, bh[0], bh[1], bh[2], bh[3]);
                ldmx4(st + ST_BLO + bo, bl[0], bl[1], bl[2], bl[3]);
#pragma unroll
                for (int p = 0; p < 2; ++p) {
                    int nj = g * 2 + p;
                    uint32_t bfh[2] = {bh[p * 2], bh[p * 2 + 1]};
                    uint32_t bfl[2] = {bl[p * 2], bl[p * 2 + 1]};
#pragma unroll
                    for (int mi = 0; mi < 2; ++mi) {
                        mma16816(acc[mi][nj], ah[mi], bfh);
                        mma16816(acc[mi][nj], ah[mi], bfl);
                        mma16816(acc[mi][nj], al[mi], bfh);
                    }
                }
            }
        }
        __syncthreads();
    }

    // ----------------- epilogue -----------------
    const int lane4 = lane >> 2;
    const int lanec = (lane & 3) * 2;
    float lsum = 0.f;

#pragma unroll
    for (int mi = 0; mi < 2; ++mi) {
        int r0g = brow + wm * 32 + mi * 16 + lane4;
        int r1g = r0g + 8;
        int rt0 = 0, rt1 = 0;
        if (EPI == 2) {
            rt0 = route[r0g & 2047];
            rt1 = route[r1g & 2047];
        }
#pragma unroll
        for (int nj = 0; nj < 8; ++nj) {
            int col = bcol + wn * 64 + nj * 8 + lanec;
            float b0 = bias[col], b1 = bias[col + 1];
            float v00 = acc[mi][nj][0] + b0, v01 = acc[mi][nj][1] + b1;
            float v10 = acc[mi][nj][2] + b0, v11 = acc[mi][nj][3] + b1;
            unsigned i0 = (unsigned)r0g * (unsigned)N + (unsigned)col;
            unsigned i1 = (unsigned)r1g * (unsigned)N + (unsigned)col;

            if (EPI == 0 || EPI == 1) {
                v00 = tanhf(v00); v01 = tanhf(v01);
                v10 = tanhf(v10); v11 = tanhf(v11);
                if (EPI == 0) {
                    v00 = dropout_val(v00, i0, key0, key1);
                    v01 = dropout_val(v01, i0 + 1, key0, key1);
                    v10 = dropout_val(v10, i1, key0, key1);
                    v11 = dropout_val(v11, i1 + 1, key0, key1);
                }
                __nv_bfloat16 h0, l0, h1, l1;
                __nv_bfloat162 ph, pl;
                split_bf16(v00, h0, l0); split_bf16(v01, h1, l1);
                ph.x = h0; ph.y = h1; pl.x = l0; pl.y = l1;
                *(__nv_bfloat162*)(Chi + i0) = ph;
                *(__nv_bfloat162*)(Clo + i0) = pl;
                split_bf16(v10, h0, l0); split_bf16(v11, h1, l1);
                ph.x = h0; ph.y = h1; pl.x = l0; pl.y = l1;
                *(__nv_bfloat162*)(Chi + i1) = ph;
                *(__nv_bfloat162*)(Clo + i1) = pl;
            } else {
                float d;
                d = hs[i0] - v00;     lsum += d * d;
                d = hs[i0 + 1] - v01; lsum += d * d;
                d = hs[i1] - v10;     lsum += d * d;
                d = hs[i1 + 1] - v11; lsum += d * d;
                if (rt0 == expert) {
                    outC[i0] = v00; outC[i0 + 1] = v01;
                }
                if (rt1 == expert) {
                    outC[i1] = v10; outC[i1 + 1] = v11;
                }
            }
        }
    }

    if (EPI == 2) {
#pragma unroll
        for (int s = 16; s > 0; s >>= 1)
            lsum += __shfl_xor_sync(0xFFFFFFFFu, lsum, s);
        if (lane == 0) atomicAdd(recon_out, lsum * recon_scale);
    }
}

// ---------------------------------------------------------------------------
// Host side: prep+wprep on default stream, then FORK -> expert0 chain on
// default stream, expert1 chain on a secondary stream -> JOIN.
// ---------------------------------------------------------------------------
extern "C" void kernel_launch(void* const* d_in, const int* in_sizes, int n_in,
                              void* d_out, int out_size)
{
    const float* x          = (const float*)d_in[0];
    const float* noise      = (const float*)d_in[1];
    const int*   route      = (const int*)  d_in[2];
    const int*   sub_choice = (const int*)  d_in[3];

    float* out   = (float*)d_out;
    float* recon = out + (out_size - 1);

    float* p_hs;
    __nv_bfloat16 *p_hs_hi, *p_hs_lo, *p_h_hi, *p_h_lo, *p_t_hi, *p_t_lo,
                  *p_s_hi, *p_s_lo, *p_w_hi, *p_w_lo;
    cudaGetSymbolAddress((void**)&p_hs,    g_hs);
    cudaGetSymbolAddress((void**)&p_hs_hi, g_hs_hi);
    cudaGetSymbolAddress((void**)&p_hs_lo, g_hs_lo);
    cudaGetSymbolAddress((void**)&p_h_hi,  g_h_hi);
    cudaGetSymbolAddress((void**)&p_h_lo,  g_h_lo);
    cudaGetSymbolAddress((void**)&p_t_hi,  g_t_hi);
    cudaGetSymbolAddress((void**)&p_t_lo,  g_t_lo);
    cudaGetSymbolAddress((void**)&p_s_hi,  g_s_hi);
    cudaGetSymbolAddress((void**)&p_s_lo,  g_s_lo);
    cudaGetSymbolAddress((void**)&p_w_hi,  g_w_hi);
    cudaGetSymbolAddress((void**)&p_w_lo,  g_w_lo);

    static cudaStream_t s1 = nullptr;
    static cudaEvent_t ev_fork = nullptr, ev_join = nullptr;
    if (s1 == nullptr) {
        cudaStreamCreateWithFlags(&s1, cudaStreamNonBlocking);
        cudaEventCreateWithFlags(&ev_fork, cudaEventDisableTiming);
        cudaEventCreateWithFlags(&ev_join, cudaEventDisableTiming);
        cudaFuncSetAttribute(gemm_tc<0>, cudaFuncAttributeMaxDynamicSharedMemorySize, SMEM_BYTES);
        cudaFuncSetAttribute(gemm_tc<1>, cudaFuncAttributeMaxDynamicSharedMemorySize, SMEM_BYTES);
        cudaFuncSetAttribute(gemm_tc<2>, cudaFuncAttributeMaxDynamicSharedMemorySize, SMEM_BYTES);
    }

    // --- exact JAX partitionable key derivation (verified R5) ---
    unsigned ek[2][2];
    threefry2x32_(0u, 42u, 0u, 0u, ek[0][0], ek[0][1]);
    threefry2x32_(0u, 42u, 0u, 1u, ek[1][0], ek[1][1]);
    unsigned kk1[2][2], kk2[2][2], kk3[2][2];
    for (int e = 0; e < 2; ++e) {
        threefry2x32_(ek[e][0], ek[e][1], 0u, 0u, kk1[e][0], kk1[e][1]);
        threefry2x32_(ek[e][0], ek[e][1], 0u, 1u, kk2[e][0], kk2[e][1]);
        threefry2x32_(ek[e][0], ek[e][1], 0u, 2u, kk3[e][0], kk3[e][1]);
    }

    prep_kernel<<<NTOT / 4 / 256, 256>>>(x, noise, route, out, recon);

    // --- fused weight prep: 12 matrices, one launch ---
    long woff[2][6];
    WPrepArgs wa;
    {
        int off = 0, m = 0;
        for (int e = 0; e < 2; ++e) {
            int base = 4 + e * 12;
            int d = (e == 0) ? 512 : 256, dh = d / 2;
            const float* srcs[6] = {
                (const float*)d_in[base + 0],
                (const float*)d_in[base + 2],
                (const float*)d_in[base + 4],
                (const float*)d_in[base + 6],
                (const float*)d_in[base + 8],
                (const float*)d_in[base + 10],
            };
            int Ks[6] = {HDIM, d, dh, d, dh, d};
            int Ns[6] = {d, dh, d, dh, d, HDIM};
            for (int wi = 0; wi < 6; ++wi, ++m) {
                woff[e][wi] = off;
                wa.src[m] = srcs[wi];
                wa.K[m] = Ks[wi];
                wa.N[m] = Ns[wi];
                wa.pref[m] = off;
                off += Ks[wi] * Ns[wi];
            }
        }
        wa.pref[12] = off;
        wprep_all<<<(off + 255) / 256, 256>>>(wa, p_w_hi, p_w_lo);
    }

    // FORK: expert 1 chain waits for prep+wprep
    cudaEventRecord(ev_fork, 0);
    cudaStreamWaitEvent(s1, ev_fork, 0);

    const float recon_scale = 1.0f / (2.0f * (float)NTOT);

    for (int e = 0; e < 2; ++e) {
        int base = 4 + e * 12;
        const float* db   = (const float*)d_in[base + 1];
        const float* s0db = (const float*)d_in[base + 3];
        const float* s0ub = (const float*)d_in[base + 5];
        const float* s1db = (const float*)d_in[base + 7];
        const float* s1ub = (const float*)d_in[base + 9];
        const float* ub   = (const float*)d_in[base + 11];
        int d = (e == 0) ? 512 : 256, dh = d / 2;
        cudaStream_t st = (e == 0) ? (cudaStream_t)0 : s1;

        // per-expert activation buffers
        __nv_bfloat16* h_hi = p_h_hi + (size_t)e * TOK * 512;
        __nv_bfloat16* h_lo = p_h_lo + (size_t)e * TOK * 512;
        __nv_bfloat16* t_hi = p_t_hi + (size_t)e * TOK * 256;
        __nv_bfloat16* t_lo = p_t_lo + (size_t)e * TOK * 256;
        __nv_bfloat16* sv_hi = p_s_hi + (size_t)e * TOK * 512;
        __nv_bfloat16* sv_lo = p_s_lo + (size_t)e * TOK * 512;

        // GEMM1: hs @ dw -> tanh -> dropout -> h
        gemm_tc<0><<<dim3(d / 128, TOK / 128), 256, SMEM_BYTES, st>>>(
            p_hs_hi, p_hs_lo, nullptr, nullptr,
            p_w_hi + woff[e][0], p_w_lo + woff[e][0], db,
            h_hi, h_lo, nullptr,
            d, HDIM, sub_choice, e, -1, kk1[e][0], kk1[e][1],
            nullptr, nullptr, nullptr, 0.f);

        // s0 branch
        gemm_tc<0><<<dim3(dh / 128, TOK / 128), 256, SMEM_BYTES, st>>>(
            h_hi, h_lo, nullptr, nullptr,
            p_w_hi + woff[e][1], p_w_lo + woff[e][1], s0db,
            t_hi, t_lo, nullptr,
            dh, d, sub_choice, e, 0, kk2[e][0], kk2[e][1],
            nullptr, nullptr, nullptr, 0.f);
        gemm_tc<1><<<dim3(d / 128, TOK / 128), 256, SMEM_BYTES, st>>>(
            t_hi, t_lo, nullptr, nullptr,
            p_w_hi + woff[e][2], p_w_lo + woff[e][2], s0ub,
            sv_hi, sv_lo, nullptr,
            d, dh, sub_choice, e, 0, 0u, 0u,
            nullptr, nullptr, nullptr, 0.f);

        // s1 branch
        gemm_tc<0><<<dim3(dh / 128, TOK / 128), 256, SMEM_BYTES, st>>>(
            h_hi, h_lo, nullptr, nullptr,
            p_w_hi + woff[e][3], p_w_lo + woff[e][3], s1db,
            t_hi, t_lo, nullptr,
            dh, d, sub_choice, e, 1, kk3[e][0], kk3[e][1],
            nullptr, nullptr, nullptr, 0.f);
        gemm_tc<1><<<dim3(d / 128, TOK / 128), 256, SMEM_BYTES, st>>>(
            t_hi, t_lo, nullptr, nullptr,
            p_w_hi + woff[e][4], p_w_lo + woff[e][4], s1ub,
            sv_hi, sv_lo, nullptr,
            d, dh, sub_choice, e, 1, 0u, 0u,
            nullptr, nullptr, nullptr, 0.f);

        // GEMM3: (choice<2 ? s : h) @ uw -> route-select out + recon
        gemm_tc<2><<<dim3(HDIM / 128, TOK / 128), 256, SMEM_BYTES, st>>>(
            h_hi, h_lo, sv_hi, sv_lo,
            p_w_hi + woff[e][5], p_w_lo + woff[e][5], ub,
            nullptr, nullptr, out,
            HDIM, d, sub_choice, e, -1, 0u, 0u,
            p_hs, route, recon, recon_scale);
    }

    // JOIN: default stream waits for expert 1 chain
    cudaEventRecord(ev_join, s1);
    cudaStreamWaitEvent(0, ev_join, 0);
}

// round 12
// speedup vs baseline: 1.4285x; 1.1055x over previous
#include <cuda_runtime.h>
#include <cuda_bf16.h>
#include <cstdint>

// ---------------------------------------------------------------------------
// Problem: x (8,2048,1024) -> 16384 tokens x 1024. Expert0 d=512, Expert1 d=256.
// Output: opt (16384*1024 fp32) + recon scalar.
// Strategy: mma.sync m16n8k16 bf16 with hi/lo split (3-MMA compensation).
// R12: term-major MMA ordering (breaks acc RAW chains), XOR-swizzled SMEM
// (no padding) enabling a 3-stage cp.async pipeline at 2 CTAs/SM.
// Expert chains overlap on parallel streams (graph fork/join).
// ---------------------------------------------------------------------------
#define TOK   16384
#define HDIM  1024
#define NTOT  (TOK * HDIM)

// ---------------- static scratch (no allocs allowed) -----------------------
__device__ float          g_hs[NTOT];
__device__ __nv_bfloat16  g_hs_hi[NTOT],          g_hs_lo[NTOT];
__device__ __nv_bfloat16  g_h_hi[2 * TOK * 512],  g_h_lo[2 * TOK * 512];
__device__ __nv_bfloat16  g_t_hi[2 * TOK * 256],  g_t_lo[2 * TOK * 256];
__device__ __nv_bfloat16  g_s_hi[2 * TOK * 512],  g_s_lo[2 * TOK * 512];
#define WTOT 2228224
__device__ __nv_bfloat16  g_w_hi[WTOT],           g_w_lo[WTOT];

// ---------------- threefry (exact JAX partitionable PRNG, verified R5) -----
__host__ __device__ __forceinline__ unsigned rotl32_(unsigned x, int r) {
    return (x << r) | (x >> (32 - r));
}
__host__ __device__ __forceinline__ void threefry2x32_(
    unsigned k0, unsigned k1, unsigned x0, unsigned x1,
    unsigned& o0, unsigned& o1)
{
    unsigned ks2 = k0 ^ k1 ^ 0x1BD11BDAu;
    unsigned ks[3] = {k0, k1, ks2};
    x0 += k0; x1 += k1;
    const int RA[4] = {13, 15, 26, 6};
    const int RB[4] = {17, 29, 16, 24};
#pragma unroll
    for (int r = 0; r < 5; ++r) {
        const int* R = (r & 1) ? RB : RA;
#pragma unroll
        for (int j = 0; j < 4; ++j) {
            x0 += x1; x1 = rotl32_(x1, R[j]); x1 ^= x0;
        }
        x0 += ks[(r + 1) % 3];
        x1 += ks[(r + 2) % 3] + (unsigned)(r + 1);
    }
    o0 = x0; o1 = x1;
}
__device__ __forceinline__ float dropout_val(
    float v, unsigned i, unsigned k0, unsigned k1)
{
    unsigned o0, o1;
    threefry2x32_(k0, k1, 0u, i, o0, o1);
    unsigned bits = o0 ^ o1;
    float u = __uint_as_float((bits >> 9) | 0x3f800000u) - 1.0f;
    return (u < 0.8f) ? (v * 1.25f) : 0.0f;
}

__device__ __forceinline__ void split_bf16(float a, __nv_bfloat16& hi, __nv_bfloat16& lo) {
    hi = __float2bfloat16(a);
    lo = __float2bfloat16(a - __bfloat162float(hi));
}

// ---------------- PTX helpers (all plain sm_80-era ISA) --------------------
__device__ __forceinline__ uint32_t smem_u32(const void* p) {
    uint32_t a;
    asm("{ .reg .u64 t; cvta.to.shared.u64 t, %1; cvt.u32.u64 %0, t; }"
        : "=r"(a) : "l"(p));
    return a;
}
__device__ __forceinline__ void cp16(uint32_t s, const void* g) {
    asm volatile("cp.async.cg.shared.global [%0], [%1], 16;"
                 :: "r"(s), "l"(g));
}
__device__ __forceinline__ void cp_commit() {
    asm volatile("cp.async.commit_group;" ::: "memory");
}
template <int N>
__device__ __forceinline__ void cp_wait() {
    asm volatile("cp.async.wait_group %0;" :: "n"(N) : "memory");
}
__device__ __forceinline__ void ldmx4(uint32_t a, uint32_t& r0, uint32_t& r1,
                                      uint32_t& r2, uint32_t& r3) {
    asm volatile("ldmatrix.sync.aligned.m8n8.x4.shared.b16 {%0,%1,%2,%3}, [%4];"
                 : "=r"(r0), "=r"(r1), "=r"(r2), "=r"(r3) : "r"(a));
}
__device__ __forceinline__ void mma16816(float* c, const uint32_t* a,
                                         const uint32_t* b) {
    asm volatile(
        "mma.sync.aligned.m16n8k16.row.col.f32.bf16.bf16.f32 "
        "{%0,%1,%2,%3}, {%4,%5,%6,%7}, {%8,%9}, {%0,%1,%2,%3};"
        : "+f"(c[0]), "+f"(c[1]), "+f"(c[2]), "+f"(c[3])
        : "r"(a[0]), "r"(a[1]), "r"(a[2]), "r"(a[3]), "r"(b[0]), "r"(b[1]));
}

// ---------------------------------------------------------------------------
// Prep: hs = x + 0.002*noise (fp32 + bf16 hi/lo); out init (route==2); recon=0
// ---------------------------------------------------------------------------
__global__ void prep_kernel(const float* __restrict__ x,
                            const float* __restrict__ noise,
                            const int*   __restrict__ route,
                            float* __restrict__ out,
                            float* __restrict__ recon)
{
    unsigned i4 = blockIdx.x * blockDim.x + threadIdx.x;
    unsigned base = i4 * 4u;
    if (base < (unsigned)NTOT) {
        float4 xv = *(const float4*)(x + base);
        float4 nv = *(const float4*)(noise + base);
        float4 h;
        h.x = xv.x + 0.002f * nv.x;
        h.y = xv.y + 0.002f * nv.y;
        h.z = xv.z + 0.002f * nv.z;
        h.w = xv.w + 0.002f * nv.w;
        *(float4*)(g_hs + base) = h;
        __nv_bfloat16 hi[4], lo[4];
        split_bf16(h.x, hi[0], lo[0]);
        split_bf16(h.y, hi[1], lo[1]);
        split_bf16(h.z, hi[2], lo[2]);
        split_bf16(h.w, hi[3], lo[3]);
        *(uint2*)(g_hs_hi + base) = *(uint2*)hi;
        *(uint2*)(g_hs_lo + base) = *(uint2*)lo;
        int s = (int)((base >> 10) & 2047u);
        float4 o = (route[s] == 2) ? h : make_float4(0.f, 0.f, 0.f, 0.f);
        *(float4*)(out + base) = o;
    }
    if (i4 == 0) *recon = 0.0f;
}

// ---------------------------------------------------------------------------
// Fused weight prep: all 12 matrices W[K,N] fp32 -> Whi/Wlo[N,K] bf16
// ---------------------------------------------------------------------------
struct WPrepArgs {
    const float* src[12];
    int K[12];
    int N[12];
    int pref[13];
};

__global__ void wprep_all(WPrepArgs a,
                          __nv_bfloat16* __restrict__ hi,
                          __nv_bfloat16* __restrict__ lo)
{
    int i = blockIdx.x * 256 + threadIdx.x;
    if (i >= a.pref[12]) return;
    int m = 0;
#pragma unroll
    for (int t = 0; t < 12; ++t)
        if (i >= a.pref[t + 1]) m = t + 1;
    int j = i - a.pref[m];
    int K = a.K[m], N = a.N[m];
    int n = j / K, k = j - n * K;
    float v = a.src[m][(size_t)k * N + n];
    __nv_bfloat16 h, l;
    split_bf16(v, h, l);
    hi[i] = h; lo[i] = l;
}

// ---------------------------------------------------------------------------
// HMMA GEMM: tile 128x128, BK=32, 8 warps (4m x 2n), warp tile 32x64.
// 3-stage cp.async pipeline, XOR-swizzled 64B rows (conflict-free for both
// cp.async stores and ldmatrix reads), term-major MMA ordering.
// __launch_bounds__(256, 2): 2 CTAs/SM (smem 2x96KB).
// ---------------------------------------------------------------------------
#define TILE_B    8192                 // 128 rows x 64 bytes
#define ST_AHI    0
#define ST_ALO    (TILE_B)
#define ST_BHI    (2 * TILE_B)
#define ST_BLO    (3 * TILE_B)
#define STAGE_B   (4 * TILE_B)         // 32768
#define SMEM_BYTES (3 * STAGE_B)       // 98304

// swizzle: 16B chunk c of row r stored at chunk (c ^ ((r>>1)&3))
__device__ __forceinline__ uint32_t sw_off(int r, int c) {
    return (uint32_t)(r * 64) + (uint32_t)((c ^ ((r >> 1) & 3)) << 4);
}

__device__ __forceinline__ void issue_stage(
    uint32_t sb, const __nv_bfloat16* Ahi, const __nv_bfloat16* Alo,
    const __nv_bfloat16* Bhi, const __nv_bfloat16* Blo,
    int brow, int bcol, int K, int k0, int tid)
{
#pragma unroll
    for (int it = 0; it < 2; ++it) {
        int idx = it * 256 + tid;          // 0..511
        int r = idx >> 2, c = idx & 3;
        uint32_t so = sw_off(r, c);
        size_t ga = (size_t)(brow + r) * K + k0 + c * 8;
        size_t gb = (size_t)(bcol + r) * K + k0 + c * 8;
        cp16(sb + ST_AHI + so, Ahi + ga);
        cp16(sb + ST_ALO + so, Alo + ga);
        cp16(sb + ST_BHI + so, Bhi + gb);
        cp16(sb + ST_BLO + so, Blo + gb);
    }
    cp_commit();
}

template <int EPI>
__global__ void __launch_bounds__(256, 2)
gemm_tc(const __nv_bfloat16* __restrict__ Ahi, const __nv_bfloat16* __restrict__ Alo,
        const __nv_bfloat16* __restrict__ A1hi, const __nv_bfloat16* __restrict__ A1lo,
        const __nv_bfloat16* __restrict__ Bhi, const __nv_bfloat16* __restrict__ Blo,
        const float* __restrict__ bias,
        __nv_bfloat16* __restrict__ Chi, __nv_bfloat16* __restrict__ Clo,
        float* __restrict__ outC,
        int N, int K,
        const int* __restrict__ sub_choice, int expert, int branch_req,
        unsigned key0, unsigned key1,
        const float* __restrict__ hs, const int* __restrict__ route,
        float* __restrict__ recon_out, float recon_scale)
{
    if (branch_req >= 0 && sub_choice[expert] != branch_req) return;
    if (EPI == 2 && sub_choice[expert] < 2) { Ahi = A1hi; Alo = A1lo; }

    extern __shared__ char smem[];
    uint32_t sbase = smem_u32(smem);

    const int tid = threadIdx.x;
    const int wid = tid >> 5, lane = tid & 31;
    const int wm = wid >> 1, wn = wid & 1;
    const int brow = blockIdx.y * 128, bcol = blockIdx.x * 128;

    float acc[2][8][4];
#pragma unroll
    for (int mi = 0; mi < 2; ++mi)
#pragma unroll
        for (int nj = 0; nj < 8; ++nj)
#pragma unroll
            for (int c = 0; c < 4; ++c) acc[mi][nj][c] = 0.f;

    // ldmatrix lane geometry
    const int a_row = wm * 32 + (lane & 15);            // + mi*16
    const int a_cb  = lane >> 4;                         // chunk add 0/1
    const int b_row = wn * 64 + (lane & 7) + ((lane >> 4) << 3);  // + g*16
    const int b_cb  = (lane >> 3) & 1;

    const int nch = K >> 5;
    issue_stage(sbase,           Ahi, Alo, Bhi, Blo, brow, bcol, K, 0,  tid);
    issue_stage(sbase + STAGE_B, Ahi, Alo, Bhi, Blo, brow, bcol, K, 32, tid);

    int rs = 0, ws = 2;
    for (int kc = 0; kc < nch; ++kc) {
        if (kc + 1 < nch) cp_wait<1>(); else cp_wait<0>();
        __syncthreads();

        uint32_t st = sbase + (uint32_t)rs * STAGE_B;
#pragma unroll
        for (int kk = 0; kk < 2; ++kk) {
            uint32_t ah[2][4], al[2][4];
#pragma unroll
            for (int mi = 0; mi < 2; ++mi) {
                uint32_t ao = sw_off(a_row + mi * 16, kk * 2 + a_cb);
                ldmx4(st + ST_AHI + ao, ah[mi][0], ah[mi][1], ah[mi][2], ah[mi][3]);
                ldmx4(st + ST_ALO + ao, al[mi][0], al[mi][1], al[mi][2], al[mi][3]);
            }
#pragma unroll
            for (int g = 0; g < 4; ++g) {
                uint32_t bo = sw_off(b_row + g * 16, kk * 2 + b_cb);
                uint32_t bh[4], bl[4];
                ldmx4(st + ST_BHI + bo, bh[0], bh[1], bh[2], bh[3]);
                ldmx4(st + ST_BLO + bo, bl[0], bl[1], bl[2], bl[3]);
                // term-major ordering: 4 independent MMAs between any
                // dependent pair on the same accumulator (hh -> hl -> lh).
#pragma unroll
                for (int p = 0; p < 2; ++p)
#pragma unroll
                    for (int mi = 0; mi < 2; ++mi)
                        mma16816(acc[mi][g * 2 + p], ah[mi], &bh[p * 2]);
#pragma unroll
                for (int p = 0; p < 2; ++p)
#pragma unroll
                    for (int mi = 0; mi < 2; ++mi)
                        mma16816(acc[mi][g * 2 + p], ah[mi], &bl[p * 2]);
#pragma unroll
                for (int p = 0; p < 2; ++p)
#pragma unroll
                    for (int mi = 0; mi < 2; ++mi)
                        mma16816(acc[mi][g * 2 + p], al[mi], &bh[p * 2]);
            }
        }
        __syncthreads();

        if (kc + 2 < nch)
            issue_stage(sbase + (uint32_t)ws * STAGE_B,
                        Ahi, Alo, Bhi, Blo, brow, bcol, K, (kc + 2) << 5, tid);
        rs = (rs == 2) ? 0 : rs + 1;
        ws = (ws == 2) ? 0 : ws + 1;
    }

    // ----------------- epilogue -----------------
    const int lane4 = lane >> 2;
    const int lanec = (lane & 3) * 2;
    float lsum = 0.f;

#pragma unroll
    for (int mi = 0; mi < 2; ++mi) {
        int r0g = brow + wm * 32 + mi * 16 + lane4;
        int r1g = r0g + 8;
        int rt0 = 0, rt1 = 0;
        if (EPI == 2) {
            rt0 = route[r0g & 2047];
            rt1 = route[r1g & 2047];
        }
#pragma unroll
        for (int nj = 0; nj < 8; ++nj) {
            int col = bcol + wn * 64 + nj * 8 + lanec;
            float b0 = bias[col], b1 = bias[col + 1];
            float v00 = acc[mi][nj][0] + b0, v01 = acc[mi][nj][1] + b1;
            float v10 = acc[mi][nj][2] + b0, v11 = acc[mi][nj][3] + b1;
            unsigned i0 = (unsigned)r0g * (unsigned)N + (unsigned)col;
            unsigned i1 = (unsigned)r1g * (unsigned)N + (unsigned)col;

            if (EPI == 0 || EPI == 1) {
                v00 = tanhf(v00); v01 = tanhf(v01);
                v10 = tanhf(v10); v11 = tanhf(v11);
                if (EPI == 0) {
                    v00 = dropout_val(v00, i0, key0, key1);
                    v01 = dropout_val(v01, i0 + 1, key0, key1);
                    v10 = dropout_val(v10, i1, key0, key1);
                    v11 = dropout_val(v11, i1 + 1, key0, key1);
                }
                __nv_bfloat16 h0, l0, h1, l1;
                __nv_bfloat162 ph, pl;
                split_bf16(v00, h0, l0); split_bf16(v01, h1, l1);
                ph.x = h0; ph.y = h1; pl.x = l0; pl.y = l1;
                *(__nv_bfloat162*)(Chi + i0) = ph;
                *(__nv_bfloat162*)(Clo + i0) = pl;
                split_bf16(v10, h0, l0); split_bf16(v11, h1, l1);
                ph.x = h0; ph.y = h1; pl.x = l0; pl.y = l1;
                *(__nv_bfloat162*)(Chi + i1) = ph;
                *(__nv_bfloat162*)(Clo + i1) = pl;
            } else {
                float d;
                d = hs[i0] - v00;     lsum += d * d;
                d = hs[i0 + 1] - v01; lsum += d * d;
                d = hs[i1] - v10;     lsum += d * d;
                d = hs[i1 + 1] - v11; lsum += d * d;
                if (rt0 == expert) {
                    outC[i0] = v00; outC[i0 + 1] = v01;
                }
                if (rt1 == expert) {
                    outC[i1] = v10; outC[i1 + 1] = v11;
                }
            }
        }
    }

    if (EPI == 2) {
#pragma unroll
        for (int s = 16; s > 0; s >>= 1)
            lsum += __shfl_xor_sync(0xFFFFFFFFu, lsum, s);
        if (lane == 0) atomicAdd(recon_out, lsum * recon_scale);
    }
}

// ---------------------------------------------------------------------------
// Host side: prep+wprep on default stream, FORK -> expert0 on default,
// expert1 on secondary stream -> JOIN.
// ---------------------------------------------------------------------------
extern "C" void kernel_launch(void* const* d_in, const int* in_sizes, int n_in,
                              void* d_out, int out_size)
{
    const float* x          = (const float*)d_in[0];
    const float* noise      = (const float*)d_in[1];
    const int*   route      = (const int*)  d_in[2];
    const int*   sub_choice = (const int*)  d_in[3];

    float* out   = (float*)d_out;
    float* recon = out + (out_size - 1);

    float* p_hs;
    __nv_bfloat16 *p_hs_hi, *p_hs_lo, *p_h_hi, *p_h_lo, *p_t_hi, *p_t_lo,
                  *p_s_hi, *p_s_lo, *p_w_hi, *p_w_lo;
    cudaGetSymbolAddress((void**)&p_hs,    g_hs);
    cudaGetSymbolAddress((void**)&p_hs_hi, g_hs_hi);
    cudaGetSymbolAddress((void**)&p_hs_lo, g_hs_lo);
    cudaGetSymbolAddress((void**)&p_h_hi,  g_h_hi);
    cudaGetSymbolAddress((void**)&p_h_lo,  g_h_lo);
    cudaGetSymbolAddress((void**)&p_t_hi,  g_t_hi);
    cudaGetSymbolAddress((void**)&p_t_lo,  g_t_lo);
    cudaGetSymbolAddress((void**)&p_s_hi,  g_s_hi);
    cudaGetSymbolAddress((void**)&p_s_lo,  g_s_lo);
    cudaGetSymbolAddress((void**)&p_w_hi,  g_w_hi);
    cudaGetSymbolAddress((void**)&p_w_lo,  g_w_lo);

    static cudaStream_t s1 = nullptr;
    static cudaEvent_t ev_fork = nullptr, ev_join = nullptr;
    if (s1 == nullptr) {
        cudaStreamCreateWithFlags(&s1, cudaStreamNonBlocking);
        cudaEventCreateWithFlags(&ev_fork, cudaEventDisableTiming);
        cudaEventCreateWithFlags(&ev_join, cudaEventDisableTiming);
        cudaFuncSetAttribute(gemm_tc<0>, cudaFuncAttributeMaxDynamicSharedMemorySize, SMEM_BYTES);
        cudaFuncSetAttribute(gemm_tc<1>, cudaFuncAttributeMaxDynamicSharedMemorySize, SMEM_BYTES);
        cudaFuncSetAttribute(gemm_tc<2>, cudaFuncAttributeMaxDynamicSharedMemorySize, SMEM_BYTES);
    }

    // --- exact JAX partitionable key derivation (verified R5) ---
    unsigned ek[2][2];
    threefry2x32_(0u, 42u, 0u, 0u, ek[0][0], ek[0][1]);
    threefry2x32_(0u, 42u, 0u, 1u, ek[1][0], ek[1][1]);
    unsigned kk1[2][2], kk2[2][2], kk3[2][2];
    for (int e = 0; e < 2; ++e) {
        threefry2x32_(ek[e][0], ek[e][1], 0u, 0u, kk1[e][0], kk1[e][1]);
        threefry2x32_(ek[e][0], ek[e][1], 0u, 1u, kk2[e][0], kk2[e][1]);
        threefry2x32_(ek[e][0], ek[e][1], 0u, 2u, kk3[e][0], kk3[e][1]);
    }

    prep_kernel<<<NTOT / 4 / 256, 256>>>(x, noise, route, out, recon);

    // --- fused weight prep: 12 matrices, one launch ---
    long woff[2][6];
    WPrepArgs wa;
    {
        int off = 0, m = 0;
        for (int e = 0; e < 2; ++e) {
            int base = 4 + e * 12;
            int d = (e == 0) ? 512 : 256, dh = d / 2;
            const float* srcs[6] = {
                (const float*)d_in[base + 0],
                (const float*)d_in[base + 2],
                (const float*)d_in[base + 4],
                (const float*)d_in[base + 6],
                (const float*)d_in[base + 8],
                (const float*)d_in[base + 10],
            };
            int Ks[6] = {HDIM, d, dh, d, dh, d};
            int Ns[6] = {d, dh, d, dh, d, HDIM};
            for (int wi = 0; wi < 6; ++wi, ++m) {
                woff[e][wi] = off;
                wa.src[m] = srcs[wi];
                wa.K[m] = Ks[wi];
                wa.N[m] = Ns[wi];
                wa.pref[m] = off;
                off += Ks[wi] * Ns[wi];
            }
        }
        wa.pref[12] = off;
        wprep_all<<<(off + 255) / 256, 256>>>(wa, p_w_hi, p_w_lo);
    }

    // FORK
    cudaEventRecord(ev_fork, 0);
    cudaStreamWaitEvent(s1, ev_fork, 0);

    const float recon_scale = 1.0f / (2.0f * (float)NTOT);

    for (int e = 0; e < 2; ++e) {
        int base = 4 + e * 12;
        const float* db   = (const float*)d_in[base + 1];
        const float* s0db = (const float*)d_in[base + 3];
        const float* s0ub = (const float*)d_in[base + 5];
        const float* s1db = (const float*)d_in[base + 7];
        const float* s1ub = (const float*)d_in[base + 9];
        const float* ub   = (const float*)d_in[base + 11];
        int d = (e == 0) ? 512 : 256, dh = d / 2;
        cudaStream_t st = (e == 0) ? (cudaStream_t)0 : s1;

        __nv_bfloat16* h_hi = p_h_hi + (size_t)e * TOK * 512;
        __nv_bfloat16* h_lo = p_h_lo + (size_t)e * TOK * 512;
        __nv_bfloat16* t_hi = p_t_hi + (size_t)e * TOK * 256;
        __nv_bfloat16* t_lo = p_t_lo + (size_t)e * TOK * 256;
        __nv_bfloat16* sv_hi = p_s_hi + (size_t)e * TOK * 512;
        __nv_bfloat16* sv_lo = p_s_lo + (size_t)e * TOK * 512;

        gemm_tc<0><<<dim3(d / 128, TOK / 128), 256, SMEM_BYTES, st>>>(
            p_hs_hi, p_hs_lo, nullptr, nullptr,
            p_w_hi + woff[e][0], p_w_lo + woff[e][0], db,
            h_hi, h_lo, nullptr,
            d, HDIM, sub_choice, e, -1, kk1[e][0], kk1[e][1],
            nullptr, nullptr, nullptr, 0.f);

        gemm_tc<0><<<dim3(dh / 128, TOK / 128), 256, SMEM_BYTES, st>>>(
            h_hi, h_lo, nullptr, nullptr,
            p_w_hi + woff[e][1], p_w_lo + woff[e][1], s0db,
            t_hi, t_lo, nullptr,
            dh, d, sub_choice, e, 0, kk2[e][0], kk2[e][1],
            nullptr, nullptr, nullptr, 0.f);
        gemm_tc<1><<<dim3(d / 128, TOK / 128), 256, SMEM_BYTES, st>>>(
            t_hi, t_lo, nullptr, nullptr,
            p_w_hi + woff[e][2], p_w_lo + woff[e][2], s0ub,
            sv_hi, sv_lo, nullptr,
            d, dh, sub_choice, e, 0, 0u, 0u,
            nullptr, nullptr, nullptr, 0.f);

        gemm_tc<0><<<dim3(dh / 128, TOK / 128), 256, SMEM_BYTES, st>>>(
            h_hi, h_lo, nullptr, nullptr,
            p_w_hi + woff[e][3], p_w_lo + woff[e][3], s1db,
            t_hi, t_lo, nullptr,
            dh, d, sub_choice, e, 1, kk3[e][0], kk3[e][1],
            nullptr, nullptr, nullptr, 0.f);
        gemm_tc<1><<<dim3(d / 128, TOK / 128), 256, SMEM_BYTES, st>>>(
            t_hi, t_lo, nullptr, nullptr,
            p_w_hi + woff[e][4], p_w_lo + woff[e][4], s1ub,
            sv_hi, sv_lo, nullptr,
            d, dh, sub_choice, e, 1, 0u, 0u,
            nullptr, nullptr, nullptr, 0.f);

        gemm_tc<2><<<dim3(HDIM / 128, TOK / 128), 256, SMEM_BYTES, st>>>(
            h_hi, h_lo, sv_hi, sv_lo,
            p_w_hi + woff[e][5], p_w_lo + woff[e][5], ub,
            nullptr, nullptr, out,
            HDIM, d, sub_choice, e, -1, 0u, 0u,
            p_hs, route, recon, recon_scale);
    }

    // JOIN
    cudaEventRecord(ev_join, s1);
    cudaStreamWaitEvent(0, ev_join, 0);
}

// round 13
// speedup vs baseline: 1.4648x; 1.0254x over previous
#include <cuda_runtime.h>
#include <cuda_bf16.h>
#include <cstdint>

// ---------------------------------------------------------------------------
// Problem: x (8,2048,1024) -> 16384 tokens x 1024. Expert0 d=512, Expert1 d=256.
// Output: opt (16384*1024 fp32) + recon scalar.
// Strategy: mma.sync m16n8k16 bf16 with hi/lo split (3-MMA compensation).
// R13: single-barrier mainloop with early cp.async issue, B-fragment double
// buffering (hides LDS latency), hoisted swizzle offsets (cuts ALU).
// Expert chains overlap on parallel streams (graph fork/join).
// ---------------------------------------------------------------------------
#define TOK   16384
#define HDIM  1024
#define NTOT  (TOK * HDIM)

// ---------------- static scratch (no allocs allowed) -----------------------
__device__ float          g_hs[NTOT];
__device__ __nv_bfloat16  g_hs_hi[NTOT],          g_hs_lo[NTOT];
__device__ __nv_bfloat16  g_h_hi[2 * TOK * 512],  g_h_lo[2 * TOK * 512];
__device__ __nv_bfloat16  g_t_hi[2 * TOK * 256],  g_t_lo[2 * TOK * 256];
__device__ __nv_bfloat16  g_s_hi[2 * TOK * 512],  g_s_lo[2 * TOK * 512];
#define WTOT 2228224
__device__ __nv_bfloat16  g_w_hi[WTOT],           g_w_lo[WTOT];

// ---------------- threefry (exact JAX partitionable PRNG, verified R5) -----
__host__ __device__ __forceinline__ unsigned rotl32_(unsigned x, int r) {
    return (x << r) | (x >> (32 - r));
}
__host__ __device__ __forceinline__ void threefry2x32_(
    unsigned k0, unsigned k1, unsigned x0, unsigned x1,
    unsigned& o0, unsigned& o1)
{
    unsigned ks2 = k0 ^ k1 ^ 0x1BD11BDAu;
    unsigned ks[3] = {k0, k1, ks2};
    x0 += k0; x1 += k1;
    const int RA[4] = {13, 15, 26, 6};
    const int RB[4] = {17, 29, 16, 24};
#pragma unroll
    for (int r = 0; r < 5; ++r) {
        const int* R = (r & 1) ? RB : RA;
#pragma unroll
        for (int j = 0; j < 4; ++j) {
            x0 += x1; x1 = rotl32_(x1, R[j]); x1 ^= x0;
        }
        x0 += ks[(r + 1) % 3];
        x1 += ks[(r + 2) % 3] + (unsigned)(r + 1);
    }
    o0 = x0; o1 = x1;
}
__device__ __forceinline__ float dropout_val(
    float v, unsigned i, unsigned k0, unsigned k1)
{
    unsigned o0, o1;
    threefry2x32_(k0, k1, 0u, i, o0, o1);
    unsigned bits = o0 ^ o1;
    float u = __uint_as_float((bits >> 9) | 0x3f800000u) - 1.0f;
    return (u < 0.8f) ? (v * 1.25f) : 0.0f;
}

__device__ __forceinline__ void split_bf16(float a, __nv_bfloat16& hi, __nv_bfloat16& lo) {
    hi = __float2bfloat16(a);
    lo = __float2bfloat16(a - __bfloat162float(hi));
}

// ---------------- PTX helpers (all plain sm_80-era ISA) --------------------
__device__ __forceinline__ uint32_t smem_u32(const void* p) {
    uint32_t a;
    asm("{ .reg .u64 t; cvta.to.shared.u64 t, %1; cvt.u32.u64 %0, t; }"
        : "=r"(a) : "l"(p));
    return a;
}
__device__ __forceinline__ void cp16(uint32_t s, const void* g) {
    asm volatile("cp.async.cg.shared.global [%0], [%1], 16;"
                 :: "r"(s), "l"(g));
}
__device__ __forceinline__ void cp_commit() {
    asm volatile("cp.async.commit_group;" ::: "memory");
}
template <int N>
__device__ __forceinline__ void cp_wait() {
    asm volatile("cp.async.wait_group %0;" :: "n"(N) : "memory");
}
__device__ __forceinline__ void ldmx4(uint32_t a, uint32_t& r0, uint32_t& r1,
                                      uint32_t& r2, uint32_t& r3) {
    asm volatile("ldmatrix.sync.aligned.m8n8.x4.shared.b16 {%0,%1,%2,%3}, [%4];"
                 : "=r"(r0), "=r"(r1), "=r"(r2), "=r"(r3) : "r"(a));
}
__device__ __forceinline__ void mma16816(float* c, const uint32_t* a,
                                         const uint32_t* b) {
    asm volatile(
        "mma.sync.aligned.m16n8k16.row.col.f32.bf16.bf16.f32 "
        "{%0,%1,%2,%3}, {%4,%5,%6,%7}, {%8,%9}, {%0,%1,%2,%3};"
        : "+f"(c[0]), "+f"(c[1]), "+f"(c[2]), "+f"(c[3])
        : "r"(a[0]), "r"(a[1]), "r"(a[2]), "r"(a[3]), "r"(b[0]), "r"(b[1]));
}

// ---------------------------------------------------------------------------
// Prep: hs = x + 0.002*noise (fp32 + bf16 hi/lo); out init (route==2); recon=0
// ---------------------------------------------------------------------------
__global__ void prep_kernel(const float* __restrict__ x,
                            const float* __restrict__ noise,
                            const int*   __restrict__ route,
                            float* __restrict__ out,
                            float* __restrict__ recon)
{
    unsigned i4 = blockIdx.x * blockDim.x + threadIdx.x;
    unsigned base = i4 * 4u;
    if (base < (unsigned)NTOT) {
        float4 xv = *(const float4*)(x + base);
        float4 nv = *(const float4*)(noise + base);
        float4 h;
        h.x = xv.x + 0.002f * nv.x;
        h.y = xv.y + 0.002f * nv.y;
        h.z = xv.z + 0.002f * nv.z;
        h.w = xv.w + 0.002f * nv.w;
        *(float4*)(g_hs + base) = h;
        __nv_bfloat16 hi[4], lo[4];
        split_bf16(h.x, hi[0], lo[0]);
        split_bf16(h.y, hi[1], lo[1]);
        split_bf16(h.z, hi[2], lo[2]);
        split_bf16(h.w, hi[3], lo[3]);
        *(uint2*)(g_hs_hi + base) = *(uint2*)hi;
        *(uint2*)(g_hs_lo + base) = *(uint2*)lo;
        int s = (int)((base >> 10) & 2047u);
        float4 o = (route[s] == 2) ? h : make_float4(0.f, 0.f, 0.f, 0.f);
        *(float4*)(out + base) = o;
    }
    if (i4 == 0) *recon = 0.0f;
}

// ---------------------------------------------------------------------------
// Fused weight prep: all 12 matrices W[K,N] fp32 -> Whi/Wlo[N,K] bf16
// ---------------------------------------------------------------------------
struct WPrepArgs {
    const float* src[12];
    int K[12];
    int N[12];
    int pref[13];
};

__global__ void wprep_all(WPrepArgs a,
                          __nv_bfloat16* __restrict__ hi,
                          __nv_bfloat16* __restrict__ lo)
{
    int i = blockIdx.x * 256 + threadIdx.x;
    if (i >= a.pref[12]) return;
    int m = 0;
#pragma unroll
    for (int t = 0; t < 12; ++t)
        if (i >= a.pref[t + 1]) m = t + 1;
    int j = i - a.pref[m];
    int K = a.K[m], N = a.N[m];
    int n = j / K, k = j - n * K;
    float v = a.src[m][(size_t)k * N + n];
    __nv_bfloat16 h, l;
    split_bf16(v, h, l);
    hi[i] = h; lo[i] = l;
}

// ---------------------------------------------------------------------------
// HMMA GEMM: tile 128x128, BK=32, 8 warps (4m x 2n), warp tile 32x64.
// 3-stage cp.async pipeline with ONE barrier per iteration + early issue.
// XOR-swizzled 64B rows; hoisted ldmatrix offsets; B-fragment double buffer.
// __launch_bounds__(256, 2): 2 CTAs/SM (smem 2x96KB).
// ---------------------------------------------------------------------------
#define TILE_B    8192                 // 128 rows x 64 bytes
#define ST_AHI    0
#define ST_ALO    (TILE_B)
#define ST_BHI    (2 * TILE_B)
#define ST_BLO    (3 * TILE_B)
#define STAGE_B   (4 * TILE_B)         // 32768
#define SMEM_BYTES (3 * STAGE_B)       // 98304

// swizzle: 16B chunk c of row r stored at chunk (c ^ ((r>>1)&3))
__device__ __forceinline__ uint32_t sw_off(int r, int c) {
    return (uint32_t)(r * 64) + (uint32_t)((c ^ ((r >> 1) & 3)) << 4);
}

__device__ __forceinline__ void issue_stage(
    uint32_t sb, const __nv_bfloat16* Ahi, const __nv_bfloat16* Alo,
    const __nv_bfloat16* Bhi, const __nv_bfloat16* Blo,
    int brow, int bcol, int K, int k0, int tid)
{
#pragma unroll
    for (int it = 0; it < 2; ++it) {
        int idx = it * 256 + tid;          // 0..511
        int r = idx >> 2, c = idx & 3;
        uint32_t so = sw_off(r, c);
        size_t ga = (size_t)(brow + r) * K + k0 + c * 8;
        size_t gb = (size_t)(bcol + r) * K + k0 + c * 8;
        cp16(sb + ST_AHI + so, Ahi + ga);
        cp16(sb + ST_ALO + so, Alo + ga);
        cp16(sb + ST_BHI + so, Bhi + gb);
        cp16(sb + ST_BLO + so, Blo + gb);
    }
    cp_commit();
}

template <int EPI>
__global__ void __launch_bounds__(256, 2)
gemm_tc(const __nv_bfloat16* __restrict__ Ahi, const __nv_bfloat16* __restrict__ Alo,
        const __nv_bfloat16* __restrict__ A1hi, const __nv_bfloat16* __restrict__ A1lo,
        const __nv_bfloat16* __restrict__ Bhi, const __nv_bfloat16* __restrict__ Blo,
        const float* __restrict__ bias,
        __nv_bfloat16* __restrict__ Chi, __nv_bfloat16* __restrict__ Clo,
        float* __restrict__ outC,
        int N, int K,
        const int* __restrict__ sub_choice, int expert, int branch_req,
        unsigned key0, unsigned key1,
        const float* __restrict__ hs, const int* __restrict__ route,
        float* __restrict__ recon_out, float recon_scale)
{
    if (branch_req >= 0 && sub_choice[expert] != branch_req) return;
    if (EPI == 2 && sub_choice[expert] < 2) { Ahi = A1hi; Alo = A1lo; }

    extern __shared__ char smem[];
    uint32_t sbase = smem_u32(smem);

    const int tid = threadIdx.x;
    const int wid = tid >> 5, lane = tid & 31;
    const int wm = wid >> 1, wn = wid & 1;
    const int brow = blockIdx.y * 128, bcol = blockIdx.x * 128;

    float acc[2][8][4];
#pragma unroll
    for (int mi = 0; mi < 2; ++mi)
#pragma unroll
        for (int nj = 0; nj < 8; ++nj)
#pragma unroll
            for (int c = 0; c < 4; ++c) acc[mi][nj][c] = 0.f;

    // ldmatrix lane geometry + hoisted swizzled offsets
    const int a_row = wm * 32 + (lane & 15);
    const int a_cb  = lane >> 4;
    const int b_row = wn * 64 + (lane & 7) + ((lane >> 4) << 3);
    const int b_cb  = (lane >> 3) & 1;

    uint32_t aoff[2][2], boff[2][4];
#pragma unroll
    for (int kk = 0; kk < 2; ++kk) {
#pragma unroll
        for (int mi = 0; mi < 2; ++mi)
            aoff[kk][mi] = sw_off(a_row + mi * 16, kk * 2 + a_cb);
#pragma unroll
        for (int g = 0; g < 4; ++g)
            boff[kk][g] = sw_off(b_row + g * 16, kk * 2 + b_cb);
    }

    const int nch = K >> 5;
    issue_stage(sbase,           Ahi, Alo, Bhi, Blo, brow, bcol, K, 0,  tid);
    issue_stage(sbase + STAGE_B, Ahi, Alo, Bhi, Blo, brow, bcol, K, 32, tid);

    int rs = 0, ws = 2;
    for (int kc = 0; kc < nch; ++kc) {
        if (kc + 1 < nch) cp_wait<1>(); else cp_wait<0>();
        __syncthreads();
        // early issue: slot ws == slot (kc-1)%3, finished by all warps
        // at the barrier above.
        if (kc + 2 < nch)
            issue_stage(sbase + (uint32_t)ws * STAGE_B,
                        Ahi, Alo, Bhi, Blo, brow, bcol, K, (kc + 2) << 5, tid);

        uint32_t st = sbase + (uint32_t)rs * STAGE_B;
#pragma unroll
        for (int kk = 0; kk < 2; ++kk) {
            uint32_t ah[2][4], al[2][4];
#pragma unroll
            for (int mi = 0; mi < 2; ++mi) {
                uint32_t ao = aoff[kk][mi];
                ldmx4(st + ST_AHI + ao, ah[mi][0], ah[mi][1], ah[mi][2], ah[mi][3]);
                ldmx4(st + ST_ALO + ao, al[mi][0], al[mi][1], al[mi][2], al[mi][3]);
            }
            // B-fragment double buffer: load g+1 while computing g
            uint32_t bh[2][4], bl[2][4];
            ldmx4(st + ST_BHI + boff[kk][0], bh[0][0], bh[0][1], bh[0][2], bh[0][3]);
            ldmx4(st + ST_BLO + boff[kk][0], bl[0][0], bl[0][1], bl[0][2], bl[0][3]);
#pragma unroll
            for (int g = 0; g < 4; ++g) {
                const int cur = g & 1, nxt = cur ^ 1;
                if (g < 3) {
                    ldmx4(st + ST_BHI + boff[kk][g + 1],
                          bh[nxt][0], bh[nxt][1], bh[nxt][2], bh[nxt][3]);
                    ldmx4(st + ST_BLO + boff[kk][g + 1],
                          bl[nxt][0], bl[nxt][1], bl[nxt][2], bl[nxt][3]);
                }
                // term-major: per-acc order hh -> hl -> lh (bit-exact vs R12)
#pragma unroll
                for (int p = 0; p < 2; ++p)
#pragma unroll
                    for (int mi = 0; mi < 2; ++mi)
                        mma16816(acc[mi][g * 2 + p], ah[mi], &bh[cur][p * 2]);
#pragma unroll
                for (int p = 0; p < 2; ++p)
#pragma unroll
                    for (int mi = 0; mi < 2; ++mi)
                        mma16816(acc[mi][g * 2 + p], ah[mi], &bl[cur][p * 2]);
#pragma unroll
                for (int p = 0; p < 2; ++p)
#pragma unroll
                    for (int mi = 0; mi < 2; ++mi)
                        mma16816(acc[mi][g * 2 + p], al[mi], &bh[cur][p * 2]);
            }
        }
        rs = (rs == 2) ? 0 : rs + 1;
        ws = (ws == 2) ? 0 : ws + 1;
    }

    // ----------------- epilogue -----------------
    const int lane4 = lane >> 2;
    const int lanec = (lane & 3) * 2;
    float lsum = 0.f;

#pragma unroll
    for (int mi = 0; mi < 2; ++mi) {
        int r0g = brow + wm * 32 + mi * 16 + lane4;
        int r1g = r0g + 8;
        int rt0 = 0, rt1 = 0;
        if (EPI == 2) {
            rt0 = route[r0g & 2047];
            rt1 = route[r1g & 2047];
        }
#pragma unroll
        for (int nj = 0; nj < 8; ++nj) {
            int col = bcol + wn * 64 + nj * 8 + lanec;
            float b0 = bias[col], b1 = bias[col + 1];
            float v00 = acc[mi][nj][0] + b0, v01 = acc[mi][nj][1] + b1;
            float v10 = acc[mi][nj][2] + b0, v11 = acc[mi][nj][3] + b1;
            unsigned i0 = (unsigned)r0g * (unsigned)N + (unsigned)col;
            unsigned i1 = (unsigned)r1g * (unsigned)N + (unsigned)col;

            if (EPI == 0 || EPI == 1) {
                v00 = tanhf(v00); v01 = tanhf(v01);
                v10 = tanhf(v10); v11 = tanhf(v11);
                if (EPI == 0) {
                    v00 = dropout_val(v00, i0, key0, key1);
                    v01 = dropout_val(v01, i0 + 1, key0, key1);
                    v10 = dropout_val(v10, i1, key0, key1);
                    v11 = dropout_val(v11, i1 + 1, key0, key1);
                }
                __nv_bfloat16 h0, l0, h1, l1;
                __nv_bfloat162 ph, pl;
                split_bf16(v00, h0, l0); split_bf16(v01, h1, l1);
                ph.x = h0; ph.y = h1; pl.x = l0; pl.y = l1;
                *(__nv_bfloat162*)(Chi + i0) = ph;
                *(__nv_bfloat162*)(Clo + i0) = pl;
                split_bf16(v10, h0, l0); split_bf16(v11, h1, l1);
                ph.x = h0; ph.y = h1; pl.x = l0; pl.y = l1;
                *(__nv_bfloat162*)(Chi + i1) = ph;
                *(__nv_bfloat162*)(Clo + i1) = pl;
            } else {
                float d;
                d = hs[i0] - v00;     lsum += d * d;
                d = hs[i0 + 1] - v01; lsum += d * d;
                d = hs[i1] - v10;     lsum += d * d;
                d = hs[i1 + 1] - v11; lsum += d * d;
                if (rt0 == expert) {
                    outC[i0] = v00; outC[i0 + 1] = v01;
                }
                if (rt1 == expert) {
                    outC[i1] = v10; outC[i1 + 1] = v11;
                }
            }
        }
    }

    if (EPI == 2) {
#pragma unroll
        for (int s = 16; s > 0; s >>= 1)
            lsum += __shfl_xor_sync(0xFFFFFFFFu, lsum, s);
        if (lane == 0) atomicAdd(recon_out, lsum * recon_scale);
    }
}

// ---------------------------------------------------------------------------
// Host side: prep+wprep on default stream, FORK -> expert0 on default,
// expert1 on secondary stream -> JOIN.
// ---------------------------------------------------------------------------
extern "C" void kernel_launch(void* const* d_in, const int* in_sizes, int n_in,
                              void* d_out, int out_size)
{
    const float* x          = (const float*)d_in[0];
    const float* noise      = (const float*)d_in[1];
    const int*   route      = (const int*)  d_in[2];
    const int*   sub_choice = (const int*)  d_in[3];

    float* out   = (float*)d_out;
    float* recon = out + (out_size - 1);

    float* p_hs;
    __nv_bfloat16 *p_hs_hi, *p_hs_lo, *p_h_hi, *p_h_lo, *p_t_hi, *p_t_lo,
                  *p_s_hi, *p_s_lo, *p_w_hi, *p_w_lo;
    cudaGetSymbolAddress((void**)&p_hs,    g_hs);
    cudaGetSymbolAddress((void**)&p_hs_hi, g_hs_hi);
    cudaGetSymbolAddress((void**)&p_hs_lo, g_hs_lo);
    cudaGetSymbolAddress((void**)&p_h_hi,  g_h_hi);
    cudaGetSymbolAddress((void**)&p_h_lo,  g_h_lo);
    cudaGetSymbolAddress((void**)&p_t_hi,  g_t_hi);
    cudaGetSymbolAddress((void**)&p_t_lo,  g_t_lo);
    cudaGetSymbolAddress((void**)&p_s_hi,  g_s_hi);
    cudaGetSymbolAddress((void**)&p_s_lo,  g_s_lo);
    cudaGetSymbolAddress((void**)&p_w_hi,  g_w_hi);
    cudaGetSymbolAddress((void**)&p_w_lo,  g_w_lo);

    static cudaStream_t s1 = nullptr;
    static cudaEvent_t ev_fork = nullptr, ev_join = nullptr;
    if (s1 == nullptr) {
        cudaStreamCreateWithFlags(&s1, cudaStreamNonBlocking);
        cudaEventCreateWithFlags(&ev_fork, cudaEventDisableTiming);
        cudaEventCreateWithFlags(&ev_join, cudaEventDisableTiming);
        cudaFuncSetAttribute(gemm_tc<0>, cudaFuncAttributeMaxDynamicSharedMemorySize, SMEM_BYTES);
        cudaFuncSetAttribute(gemm_tc<1>, cudaFuncAttributeMaxDynamicSharedMemorySize, SMEM_BYTES);
        cudaFuncSetAttribute(gemm_tc<2>, cudaFuncAttributeMaxDynamicSharedMemorySize, SMEM_BYTES);
    }

    // --- exact JAX partitionable key derivation (verified R5) ---
    unsigned ek[2][2];
    threefry2x32_(0u, 42u, 0u, 0u, ek[0][0], ek[0][1]);
    threefry2x32_(0u, 42u, 0u, 1u, ek[1][0], ek[1][1]);
    unsigned kk1[2][2], kk2[2][2], kk3[2][2];
    for (int e = 0; e < 2; ++e) {
        threefry2x32_(ek[e][0], ek[e][1], 0u, 0u, kk1[e][0], kk1[e][1]);
        threefry2x32_(ek[e][0], ek[e][1], 0u, 1u, kk2[e][0], kk2[e][1]);
        threefry2x32_(ek[e][0], ek[e][1], 0u, 2u, kk3[e][0], kk3[e][1]);
    }

    prep_kernel<<<NTOT / 4 / 256, 256>>>(x, noise, route, out, recon);

    // --- fused weight prep: 12 matrices, one launch ---
    long woff[2][6];
    WPrepArgs wa;
    {
        int off = 0, m = 0;
        for (int e = 0; e < 2; ++e) {
            int base = 4 + e * 12;
            int d = (e == 0) ? 512 : 256, dh = d / 2;
            const float* srcs[6] = {
                (const float*)d_in[base + 0],
                (const float*)d_in[base + 2],
                (const float*)d_in[base + 4],
                (const float*)d_in[base + 6],
                (const float*)d_in[base + 8],
                (const float*)d_in[base + 10],
            };
            int Ks[6] = {HDIM, d, dh, d, dh, d};
            int Ns[6] = {d, dh, d, dh, d, HDIM};
            for (int wi = 0; wi < 6; ++wi, ++m) {
                woff[e][wi] = off;
                wa.src[m] = srcs[wi];
                wa.K[m] = Ks[wi];
                wa.N[m] = Ns[wi];
                wa.pref[m] = off;
                off += Ks[wi] * Ns[wi];
            }
        }
        wa.pref[12] = off;
        wprep_all<<<(off + 255) / 256, 256>>>(wa, p_w_hi, p_w_lo);
    }

    // FORK
    cudaEventRecord(ev_fork, 0);
    cudaStreamWaitEvent(s1, ev_fork, 0);

    const float recon_scale = 1.0f / (2.0f * (float)NTOT);

    for (int e = 0; e < 2; ++e) {
        int base = 4 + e * 12;
        const float* db   = (const float*)d_in[base + 1];
        const float* s0db = (const float*)d_in[base + 3];
        const float* s0ub = (const float*)d_in[base + 5];
        const float* s1db = (const float*)d_in[base + 7];
        const float* s1ub = (const float*)d_in[base + 9];
        const float* ub   = (const float*)d_in[base + 11];
        int d = (e == 0) ? 512 : 256, dh = d / 2;
        cudaStream_t st = (e == 0) ? (cudaStream_t)0 : s1;

        __nv_bfloat16* h_hi = p_h_hi + (size_t)e * TOK * 512;
        __nv_bfloat16* h_lo = p_h_lo + (size_t)e * TOK * 512;
        __nv_bfloat16* t_hi = p_t_hi + (size_t)e * TOK * 256;
        __nv_bfloat16* t_lo = p_t_lo + (size_t)e * TOK * 256;
        __nv_bfloat16* sv_hi = p_s_hi + (size_t)e * TOK * 512;
        __nv_bfloat16* sv_lo = p_s_lo + (size_t)e * TOK * 512;

        gemm_tc<0><<<dim3(d / 128, TOK / 128), 256, SMEM_BYTES, st>>>(
            p_hs_hi, p_hs_lo, nullptr, nullptr,
            p_w_hi + woff[e][0], p_w_lo + woff[e][0], db,
            h_hi, h_lo, nullptr,
            d, HDIM, sub_choice, e, -1, kk1[e][0], kk1[e][1],
            nullptr, nullptr, nullptr, 0.f);

        gemm_tc<0><<<dim3(dh / 128, TOK / 128), 256, SMEM_BYTES, st>>>(
            h_hi, h_lo, nullptr, nullptr,
            p_w_hi + woff[e][1], p_w_lo + woff[e][1], s0db,
            t_hi, t_lo, nullptr,
            dh, d, sub_choice, e, 0, kk2[e][0], kk2[e][1],
            nullptr, nullptr, nullptr, 0.f);
        gemm_tc<1><<<dim3(d / 128, TOK / 128), 256, SMEM_BYTES, st>>>(
            t_hi, t_lo, nullptr, nullptr,
            p_w_hi + woff[e][2], p_w_lo + woff[e][2], s0ub,
            sv_hi, sv_lo, nullptr,
            d, dh, sub_choice, e, 0, 0u, 0u,
            nullptr, nullptr, nullptr, 0.f);

        gemm_tc<0><<<dim3(dh / 128, TOK / 128), 256, SMEM_BYTES, st>>>(
            h_hi, h_lo, nullptr, nullptr,
            p_w_hi + woff[e][3], p_w_lo + woff[e][3], s1db,
            t_hi, t_lo, nullptr,
            dh, d, sub_choice, e, 1, kk3[e][0], kk3[e][1],
            nullptr, nullptr, nullptr, 0.f);
        gemm_tc<1><<<dim3(d / 128, TOK / 128), 256, SMEM_BYTES, st>>>(
            t_hi, t_lo, nullptr, nullptr,
            p_w_hi + woff[e][4], p_w_lo + woff[e][4], s1ub,
            sv_hi, sv_lo, nullptr,
            d, dh, sub_choice, e, 1, 0u, 0u,
            nullptr, nullptr, nullptr, 0.f);

        gemm_tc<2><<<dim3(HDIM / 128, TOK / 128), 256, SMEM_BYTES, st>>>(
            h_hi, h_lo, sv_hi, sv_lo,
            p_w_hi + woff[e][5], p_w_lo + woff[e][5], ub,
            nullptr, nullptr, out,
            HDIM, d, sub_choice, e, -1, 0u, 0u,
            p_hs, route, recon, recon_scale);
    }

    // JOIN
    cudaEventRecord(ev_join, s1);
    cudaStreamWaitEvent(0, ev_join, 0);
}

// round 14
// speedup vs baseline: 1.8689x; 1.2759x over previous
#include <cuda_runtime.h>
#include <cuda_fp16.h>
#include <cstdint>

// ---------------------------------------------------------------------------
// Problem: x (8,2048,1024) -> 16384 tokens x 1024. Expert0 d=512, Expert1 d=256.
// Output: opt (16384*1024 fp32) + recon scalar.
// R14: fp16 2-MMA scheme. Weights split hi/lo in fp16 (pre-scaled by 64 to
// keep lo out of subnormal range; epilogue multiplies by 1/64), activations
// single fp16. MMA work drops to 2/3 of the bf16 3-term scheme; activation
// traffic halves; 4-stage cp.async pipeline in the same 96KB smem.
// Expert chains overlap on parallel streams (graph fork/join).
// ---------------------------------------------------------------------------
#define TOK   16384
#define HDIM  1024
#define NTOT  (TOK * HDIM)
#define WSCALE     64.0f
#define INV_WSCALE (1.0f / 64.0f)

// ---------------- static scratch (no allocs allowed) -----------------------
__device__ float   g_hs[NTOT];
__device__ __half  g_hs16[NTOT];
__device__ __half  g_h16[2 * TOK * 512];
__device__ __half  g_t16[2 * TOK * 256];
__device__ __half  g_s16[2 * TOK * 512];
#define WTOT 2228224
__device__ __half  g_w_hi[WTOT], g_w_lo[WTOT];

// ---------------- threefry (exact JAX partitionable PRNG, verified R5) -----
__host__ __device__ __forceinline__ unsigned rotl32_(unsigned x, int r) {
    return (x << r) | (x >> (32 - r));
}
__host__ __device__ __forceinline__ void threefry2x32_(
    unsigned k0, unsigned k1, unsigned x0, unsigned x1,
    unsigned& o0, unsigned& o1)
{
    unsigned ks2 = k0 ^ k1 ^ 0x1BD11BDAu;
    unsigned ks[3] = {k0, k1, ks2};
    x0 += k0; x1 += k1;
    const int RA[4] = {13, 15, 26, 6};
    const int RB[4] = {17, 29, 16, 24};
#pragma unroll
    for (int r = 0; r < 5; ++r) {
        const int* R = (r & 1) ? RB : RA;
#pragma unroll
        for (int j = 0; j < 4; ++j) {
            x0 += x1; x1 = rotl32_(x1, R[j]); x1 ^= x0;
        }
        x0 += ks[(r + 1) % 3];
        x1 += ks[(r + 2) % 3] + (unsigned)(r + 1);
    }
    o0 = x0; o1 = x1;
}
__device__ __forceinline__ float dropout_val(
    float v, unsigned i, unsigned k0, unsigned k1)
{
    unsigned o0, o1;
    threefry2x32_(k0, k1, 0u, i, o0, o1);
    unsigned bits = o0 ^ o1;
    float u = __uint_as_float((bits >> 9) | 0x3f800000u) - 1.0f;
    return (u < 0.8f) ? (v * 1.25f) : 0.0f;
}

// ---------------- PTX helpers (all plain sm_80-era ISA) --------------------
__device__ __forceinline__ uint32_t smem_u32(const void* p) {
    uint32_t a;
    asm("{ .reg .u64 t; cvta.to.shared.u64 t, %1; cvt.u32.u64 %0, t; }"
        : "=r"(a) : "l"(p));
    return a;
}
__device__ __forceinline__ void cp16(uint32_t s, const void* g) {
    asm volatile("cp.async.cg.shared.global [%0], [%1], 16;"
                 :: "r"(s), "l"(g));
}
__device__ __forceinline__ void cp_commit() {
    asm volatile("cp.async.commit_group;" ::: "memory");
}
template <int N>
__device__ __forceinline__ void cp_wait() {
    asm volatile("cp.async.wait_group %0;" :: "n"(N) : "memory");
}
__device__ __forceinline__ void ldmx4(uint32_t a, uint32_t& r0, uint32_t& r1,
                                      uint32_t& r2, uint32_t& r3) {
    asm volatile("ldmatrix.sync.aligned.m8n8.x4.shared.b16 {%0,%1,%2,%3}, [%4];"
                 : "=r"(r0), "=r"(r1), "=r"(r2), "=r"(r3) : "r"(a));
}
__device__ __forceinline__ void mma16816(float* c, const uint32_t* a,
                                         const uint32_t* b) {
    asm volatile(
        "mma.sync.aligned.m16n8k16.row.col.f32.f16.f16.f32 "
        "{%0,%1,%2,%3}, {%4,%5,%6,%7}, {%8,%9}, {%0,%1,%2,%3};"
        : "+f"(c[0]), "+f"(c[1]), "+f"(c[2]), "+f"(c[3])
        : "r"(a[0]), "r"(a[1]), "r"(a[2]), "r"(a[3]), "r"(b[0]), "r"(b[1]));
}

// ---------------------------------------------------------------------------
// Prep: hs = x + 0.002*noise (fp32 + fp16); out init (route==2); recon=0
// ---------------------------------------------------------------------------
__global__ void prep_kernel(const float* __restrict__ x,
                            const float* __restrict__ noise,
                            const int*   __restrict__ route,
                            float* __restrict__ out,
                            float* __restrict__ recon)
{
    unsigned i4 = blockIdx.x * blockDim.x + threadIdx.x;
    unsigned base = i4 * 4u;
    if (base < (unsigned)NTOT) {
        float4 xv = *(const float4*)(x + base);
        float4 nv = *(const float4*)(noise + base);
        float4 h;
        h.x = xv.x + 0.002f * nv.x;
        h.y = xv.y + 0.002f * nv.y;
        h.z = xv.z + 0.002f * nv.z;
        h.w = xv.w + 0.002f * nv.w;
        *(float4*)(g_hs + base) = h;
        __half hv[4];
        hv[0] = __float2half(h.x); hv[1] = __float2half(h.y);
        hv[2] = __float2half(h.z); hv[3] = __float2half(h.w);
        *(uint2*)(g_hs16 + base) = *(uint2*)hv;
        int s = (int)((base >> 10) & 2047u);
        float4 o = (route[s] == 2) ? h : make_float4(0.f, 0.f, 0.f, 0.f);
        *(float4*)(out + base) = o;
    }
    if (i4 == 0) *recon = 0.0f;
}

// ---------------------------------------------------------------------------
// Fused weight prep: 12 matrices W[K,N] fp32 -> (64*W) as fp16 hi/lo [N,K]
// ---------------------------------------------------------------------------
struct WPrepArgs {
    const float* src[12];
    int K[12];
    int N[12];
    int pref[13];
};

__global__ void wprep_all(WPrepArgs a,
                          __half* __restrict__ hi,
                          __half* __restrict__ lo)
{
    int i = blockIdx.x * 256 + threadIdx.x;
    if (i >= a.pref[12]) return;
    int m = 0;
#pragma unroll
    for (int t = 0; t < 12; ++t)
        if (i >= a.pref[t + 1]) m = t + 1;
    int j = i - a.pref[m];
    int K = a.K[m], N = a.N[m];
    int n = j / K, k = j - n * K;
    float v = a.src[m][(size_t)k * N + n] * WSCALE;
    __half h = __float2half(v);
    __half l = __float2half(v - __half2float(h));
    hi[i] = h; lo[i] = l;
}

// ---------------------------------------------------------------------------
// HMMA GEMM: tile 128x128, BK=32, 8 warps (4m x 2n), warp tile 32x64.
// fp16 2-MMA: acc += A16*Bh ; acc += A16*Bl  (B pre-scaled by 64).
// 4-stage cp.async pipeline, one barrier per iteration, early issue,
// XOR-swizzled 64B rows, hoisted offsets, B-fragment double buffer.
// __launch_bounds__(256, 2): 2 CTAs/SM (smem 2x96KB).
// ---------------------------------------------------------------------------
#define TILE_B    8192                 // 128 rows x 64 bytes
#define ST_A      0
#define ST_BH     (TILE_B)
#define ST_BL     (2 * TILE_B)
#define STAGE_B   (3 * TILE_B)         // 24576
#define NSTAGE    4
#define SMEM_BYTES (NSTAGE * STAGE_B)  // 98304

// swizzle: 16B chunk c of row r stored at chunk (c ^ ((r>>1)&3))
__device__ __forceinline__ uint32_t sw_off(int r, int c) {
    return (uint32_t)(r * 64) + (uint32_t)((c ^ ((r >> 1) & 3)) << 4);
}

__device__ __forceinline__ void issue_stage(
    uint32_t sb, const __half* A, const __half* Bhi, const __half* Blo,
    int brow, int bcol, int K, int k0, int tid)
{
#pragma unroll
    for (int it = 0; it < 2; ++it) {
        int idx = it * 256 + tid;          // 0..511
        int r = idx >> 2, c = idx & 3;
        uint32_t so = sw_off(r, c);
        size_t ga = (size_t)(brow + r) * K + k0 + c * 8;
        size_t gb = (size_t)(bcol + r) * K + k0 + c * 8;
        cp16(sb + ST_A  + so, A   + ga);
        cp16(sb + ST_BH + so, Bhi + gb);
        cp16(sb + ST_BL + so, Blo + gb);
    }
    cp_commit();
}

template <int EPI>
__global__ void __launch_bounds__(256, 2)
gemm_tc(const __half* __restrict__ A0, const __half* __restrict__ A1,
        const __half* __restrict__ Bhi, const __half* __restrict__ Blo,
        const float* __restrict__ bias,
        __half* __restrict__ C,
        float* __restrict__ outC,
        int N, int K,
        const int* __restrict__ sub_choice, int expert, int branch_req,
        unsigned key0, unsigned key1,
        const float* __restrict__ hs, const int* __restrict__ route,
        float* __restrict__ recon_out, float recon_scale)
{
    if (branch_req >= 0 && sub_choice[expert] != branch_req) return;
    const __half* A = A0;
    if (EPI == 2 && sub_choice[expert] < 2) A = A1;

    extern __shared__ char smem[];
    uint32_t sbase = smem_u32(smem);

    const int tid = threadIdx.x;
    const int wid = tid >> 5, lane = tid & 31;
    const int wm = wid >> 1, wn = wid & 1;
    const int brow = blockIdx.y * 128, bcol = blockIdx.x * 128;

    float acc[2][8][4];
#pragma unroll
    for (int mi = 0; mi < 2; ++mi)
#pragma unroll
        for (int nj = 0; nj < 8; ++nj)
#pragma unroll
            for (int c = 0; c < 4; ++c) acc[mi][nj][c] = 0.f;

    // ldmatrix lane geometry + hoisted swizzled offsets
    const int a_row = wm * 32 + (lane & 15);
    const int a_cb  = lane >> 4;
    const int b_row = wn * 64 + (lane & 7) + ((lane >> 4) << 3);
    const int b_cb  = (lane >> 3) & 1;

    uint32_t aoff[2][2], boff[2][4];
#pragma unroll
    for (int kk = 0; kk < 2; ++kk) {
#pragma unroll
        for (int mi = 0; mi < 2; ++mi)
            aoff[kk][mi] = sw_off(a_row + mi * 16, kk * 2 + a_cb);
#pragma unroll
        for (int g = 0; g < 4; ++g)
            boff[kk][g] = sw_off(b_row + g * 16, kk * 2 + b_cb);
    }

    const int nch = K >> 5;              // >= 8 for all our shapes
    issue_stage(sbase,               A, Bhi, Blo, brow, bcol, K, 0,  tid);
    issue_stage(sbase + STAGE_B,     A, Bhi, Blo, brow, bcol, K, 32, tid);
    issue_stage(sbase + 2 * STAGE_B, A, Bhi, Blo, brow, bcol, K, 64, tid);

    for (int kc = 0; kc < nch; ++kc) {
        if (kc + 2 < nch)      cp_wait<2>();
        else if (kc + 1 < nch) cp_wait<1>();
        else                   cp_wait<0>();
        __syncthreads();
        // slot (kc+3)&3 == slot (kc-1)&3: all warps finished it at the
        // barrier above -> safe to overwrite now.
        if (kc + 3 < nch)
            issue_stage(sbase + (uint32_t)((kc + 3) & 3) * STAGE_B,
                        A, Bhi, Blo, brow, bcol, K, (kc + 3) << 5, tid);

        uint32_t st = sbase + (uint32_t)(kc & 3) * STAGE_B;
#pragma unroll
        for (int kk = 0; kk < 2; ++kk) {
            uint32_t ah[2][4];
#pragma unroll
            for (int mi = 0; mi < 2; ++mi) {
                uint32_t ao = aoff[kk][mi];
                ldmx4(st + ST_A + ao, ah[mi][0], ah[mi][1], ah[mi][2], ah[mi][3]);
            }
            // B-fragment double buffer: load g+1 while computing g
            uint32_t bh[2][4], bl[2][4];
            ldmx4(st + ST_BH + boff[kk][0], bh[0][0], bh[0][1], bh[0][2], bh[0][3]);
            ldmx4(st + ST_BL + boff[kk][0], bl[0][0], bl[0][1], bl[0][2], bl[0][3]);
#pragma unroll
            for (int g = 0; g < 4; ++g) {
                const int cur = g & 1, nxt = cur ^ 1;
                if (g < 3) {
                    ldmx4(st + ST_BH + boff[kk][g + 1],
                          bh[nxt][0], bh[nxt][1], bh[nxt][2], bh[nxt][3]);
                    ldmx4(st + ST_BL + boff[kk][g + 1],
                          bl[nxt][0], bl[nxt][1], bl[nxt][2], bl[nxt][3]);
                }
                // term-major: 4 independent hh MMAs, then 4 hl MMAs
#pragma unroll
                for (int p = 0; p < 2; ++p)
#pragma unroll
                    for (int mi = 0; mi < 2; ++mi)
                        mma16816(acc[mi][g * 2 + p], ah[mi], &bh[cur][p * 2]);
#pragma unroll
                for (int p = 0; p < 2; ++p)
#pragma unroll
                    for (int mi = 0; mi < 2; ++mi)
                        mma16816(acc[mi][g * 2 + p], ah[mi], &bl[cur][p * 2]);
            }
        }
    }

    // ----------------- epilogue -----------------
    const int lane4 = lane >> 2;
    const int lanec = (lane & 3) * 2;
    float lsum = 0.f;

#pragma unroll
    for (int mi = 0; mi < 2; ++mi) {
        int r0g = brow + wm * 32 + mi * 16 + lane4;
        int r1g = r0g + 8;
        int rt0 = 0, rt1 = 0;
        if (EPI == 2) {
            rt0 = route[r0g & 2047];
            rt1 = route[r1g & 2047];
        }
#pragma unroll
        for (int nj = 0; nj < 8; ++nj) {
            int col = bcol + wn * 64 + nj * 8 + lanec;
            float b0 = bias[col], b1 = bias[col + 1];
            float v00 = acc[mi][nj][0] * INV_WSCALE + b0;
            float v01 = acc[mi][nj][1] * INV_WSCALE + b1;
            float v10 = acc[mi][nj][2] * INV_WSCALE + b0;
            float v11 = acc[mi][nj][3] * INV_WSCALE + b1;
            unsigned i0 = (unsigned)r0g * (unsigned)N + (unsigned)col;
            unsigned i1 = (unsigned)r1g * (unsigned)N + (unsigned)col;

            if (EPI == 0 || EPI == 1) {
                v00 = tanhf(v00); v01 = tanhf(v01);
                v10 = tanhf(v10); v11 = tanhf(v11);
                if (EPI == 0) {
                    v00 = dropout_val(v00, i0, key0, key1);
                    v01 = dropout_val(v01, i0 + 1, key0, key1);
                    v10 = dropout_val(v10, i1, key0, key1);
                    v11 = dropout_val(v11, i1 + 1, key0, key1);
                }
                __half2 p0, p1;
                p0.x = __float2half(v00); p0.y = __float2half(v01);
                p1.x = __float2half(v10); p1.y = __float2half(v11);
                *(__half2*)(C + i0) = p0;
                *(__half2*)(C + i1) = p1;
            } else {
                float d;
                d = hs[i0] - v00;     lsum += d * d;
                d = hs[i0 + 1] - v01; lsum += d * d;
                d = hs[i1] - v10;     lsum += d * d;
                d = hs[i1 + 1] - v11; lsum += d * d;
                if (rt0 == expert) {
                    outC[i0] = v00; outC[i0 + 1] = v01;
                }
                if (rt1 == expert) {
                    outC[i1] = v10; outC[i1 + 1] = v11;
                }
            }
        }
    }

    if (EPI == 2) {
#pragma unroll
        for (int s = 16; s > 0; s >>= 1)
            lsum += __shfl_xor_sync(0xFFFFFFFFu, lsum, s);
        if (lane == 0) atomicAdd(recon_out, lsum * recon_scale);
    }
}

// ---------------------------------------------------------------------------
// Host side: prep+wprep on default stream, FORK -> expert0 on default,
// expert1 on secondary stream -> JOIN.
// ---------------------------------------------------------------------------
extern "C" void kernel_launch(void* const* d_in, const int* in_sizes, int n_in,
                              void* d_out, int out_size)
{
    const float* x          = (const float*)d_in[0];
    const float* noise      = (const float*)d_in[1];
    const int*   route      = (const int*)  d_in[2];
    const int*   sub_choice = (const int*)  d_in[3];

    float* out   = (float*)d_out;
    float* recon = out + (out_size - 1);

    float* p_hs;
    __half *p_hs16, *p_h16, *p_t16, *p_s16, *p_w_hi, *p_w_lo;
    cudaGetSymbolAddress((void**)&p_hs,   g_hs);
    cudaGetSymbolAddress((void**)&p_hs16, g_hs16);
    cudaGetSymbolAddress((void**)&p_h16,  g_h16);
    cudaGetSymbolAddress((void**)&p_t16,  g_t16);
    cudaGetSymbolAddress((void**)&p_s16,  g_s16);
    cudaGetSymbolAddress((void**)&p_w_hi, g_w_hi);
    cudaGetSymbolAddress((void**)&p_w_lo, g_w_lo);

    static cudaStream_t s1 = nullptr;
    static cudaEvent_t ev_fork = nullptr, ev_join = nullptr;
    if (s1 == nullptr) {
        cudaStreamCreateWithFlags(&s1, cudaStreamNonBlocking);
        cudaEventCreateWithFlags(&ev_fork, cudaEventDisableTiming);
        cudaEventCreateWithFlags(&ev_join, cudaEventDisableTiming);
        cudaFuncSetAttribute(gemm_tc<0>, cudaFuncAttributeMaxDynamicSharedMemorySize, SMEM_BYTES);
        cudaFuncSetAttribute(gemm_tc<1>, cudaFuncAttributeMaxDynamicSharedMemorySize, SMEM_BYTES);
        cudaFuncSetAttribute(gemm_tc<2>, cudaFuncAttributeMaxDynamicSharedMemorySize, SMEM_BYTES);
    }

    // --- exact JAX partitionable key derivation (verified R5) ---
    unsigned ek[2][2];
    threefry2x32_(0u, 42u, 0u, 0u, ek[0][0], ek[0][1]);
    threefry2x32_(0u, 42u, 0u, 1u, ek[1][0], ek[1][1]);
    unsigned kk1[2][2], kk2[2][2], kk3[2][2];
    for (int e = 0; e < 2; ++e) {
        threefry2x32_(ek[e][0], ek[e][1], 0u, 0u, kk1[e][0], kk1[e][1]);
        threefry2x32_(ek[e][0], ek[e][1], 0u, 1u, kk2[e][0], kk2[e][1]);
        threefry2x32_(ek[e][0], ek[e][1], 0u, 2u, kk3[e][0], kk3[e][1]);
    }

    prep_kernel<<<NTOT / 4 / 256, 256>>>(x, noise, route, out, recon);

    // --- fused weight prep: 12 matrices, one launch ---
    long woff[2][6];
    WPrepArgs wa;
    {
        int off = 0, m = 0;
        for (int e = 0; e < 2; ++e) {
            int base = 4 + e * 12;
            int d = (e == 0) ? 512 : 256, dh = d / 2;
            const float* srcs[6] = {
                (const float*)d_in[base + 0],
                (const float*)d_in[base + 2],
                (const float*)d_in[base + 4],
                (const float*)d_in[base + 6],
                (const float*)d_in[base + 8],
                (const float*)d_in[base + 10],
            };
            int Ks[6] = {HDIM, d, dh, d, dh, d};
            int Ns[6] = {d, dh, d, dh, d, HDIM};
            for (int wi = 0; wi < 6; ++wi, ++m) {
                woff[e][wi] = off;
                wa.src[m] = srcs[wi];
                wa.K[m] = Ks[wi];
                wa.N[m] = Ns[wi];
                wa.pref[m] = off;
                off += Ks[wi] * Ns[wi];
            }
        }
        wa.pref[12] = off;
        wprep_all<<<(off + 255) / 256, 256>>>(wa, p_w_hi, p_w_lo);
    }

    // FORK
    cudaEventRecord(ev_fork, 0);
    cudaStreamWaitEvent(s1, ev_fork, 0);

    const float recon_scale = 1.0f / (2.0f * (float)NTOT);

    for (int e = 0; e < 2; ++e) {
        int base = 4 + e * 12;
        const float* db   = (const float*)d_in[base + 1];
        const float* s0db = (const float*)d_in[base + 3];
        const float* s0ub = (const float*)d_in[base + 5];
        const float* s1db = (const float*)d_in[base + 7];
        const float* s1ub = (const float*)d_in[base + 9];
        const float* ub   = (const float*)d_in[base + 11];
        int d = (e == 0) ? 512 : 256, dh = d / 2;
        cudaStream_t st = (e == 0) ? (cudaStream_t)0 : s1;

        __half* h16  = p_h16 + (size_t)e * TOK * 512;
        __half* t16  = p_t16 + (size_t)e * TOK * 256;
        __half* sv16 = p_s16 + (size_t)e * TOK * 512;

        // GEMM1: hs @ dw -> tanh -> dropout -> h
        gemm_tc<0><<<dim3(d / 128, TOK / 128), 256, SMEM_BYTES, st>>>(
            p_hs16, nullptr,
            p_w_hi + woff[e][0], p_w_lo + woff[e][0], db,
            h16, nullptr,
            d, HDIM, sub_choice, e, -1, kk1[e][0], kk1[e][1],
            nullptr, nullptr, nullptr, 0.f);

        // s0 branch
        gemm_tc<0><<<dim3(dh / 128, TOK / 128), 256, SMEM_BYTES, st>>>(
            h16, nullptr,
            p_w_hi + woff[e][1], p_w_lo + woff[e][1], s0db,
            t16, nullptr,
            dh, d, sub_choice, e, 0, kk2[e][0], kk2[e][1],
            nullptr, nullptr, nullptr, 0.f);
        gemm_tc<1><<<dim3(d / 128, TOK / 128), 256, SMEM_BYTES, st>>>(
            t16, nullptr,
            p_w_hi + woff[e][2], p_w_lo + woff[e][2], s0ub,
            sv16, nullptr,
            d, dh, sub_choice, e, 0, 0u, 0u,
            nullptr, nullptr, nullptr, 0.f);

        // s1 branch
        gemm_tc<0><<<dim3(dh / 128, TOK / 128), 256, SMEM_BYTES, st>>>(
            h16, nullptr,
            p_w_hi + woff[e][3], p_w_lo + woff[e][3], s1db,
            t16, nullptr,
            dh, d, sub_choice, e, 1, kk3[e][0], kk3[e][1],
            nullptr, nullptr, nullptr, 0.f);
        gemm_tc<1><<<dim3(d / 128, TOK / 128), 256, SMEM_BYTES, st>>>(
            t16, nullptr,
            p_w_hi + woff[e][4], p_w_lo + woff[e][4], s1ub,
            sv16, nullptr,
            d, dh, sub_choice, e, 1, 0u, 0u,
            nullptr, nullptr, nullptr, 0.f);

        // GEMM3: (choice<2 ? s : h) @ uw -> route-select out + recon
        gemm_tc<2><<<dim3(HDIM / 128, TOK / 128), 256, SMEM_BYTES, st>>>(
            h16, sv16,
            p_w_hi + woff[e][5], p_w_lo + woff[e][5], ub,
            nullptr, out,
            HDIM, d, sub_choice, e, -1, 0u, 0u,
            p_hs, route, recon, recon_scale);
    }

    // JOIN
    cudaEventRecord(ev_join, s1);
    cudaStreamWaitEvent(0, ev_join, 0);
}

// round 15
// speedup vs baseline: 2.6025x; 1.3925x over previous
#include <cuda_runtime.h>
#include <cuda_fp16.h>
#include <cstdint>

// ---------------------------------------------------------------------------
// Problem: x (8,2048,1024) -> 16384 tokens x 1024. Expert0 d=512, Expert1 d=256.
// Output: opt (16384*1024 fp32) + recon scalar.
// R15: pure fp16 single-MMA GEMMs (weights AND activations fp16; error budget
// verified: R14 measured 2.43e-4 from activations alone, weights add ~2.8e-4
// independent -> ~3.5e-4 total vs 1e-3 threshold). BK=64 (128B smem rows,
// swizzle c^(r&7)) halves barrier/issue overhead per K. 3-stage pipeline,
// 2 CTAs/SM. Expert chains overlap on parallel streams (graph fork/join).
// ---------------------------------------------------------------------------
#define TOK   16384
#define HDIM  1024
#define NTOT  (TOK * HDIM)

// ---------------- static scratch (no allocs allowed) -----------------------
__device__ float   g_hs[NTOT];
__device__ __half  g_hs16[NTOT];
__device__ __half  g_h16[2 * TOK * 512];
__device__ __half  g_t16[2 * TOK * 256];
__device__ __half  g_s16[2 * TOK * 512];
#define WTOT 2228224
__device__ __half  g_w16[WTOT];

// ---------------- threefry (exact JAX partitionable PRNG, verified R5) -----
__host__ __device__ __forceinline__ unsigned rotl32_(unsigned x, int r) {
    return (x << r) | (x >> (32 - r));
}
__host__ __device__ __forceinline__ void threefry2x32_(
    unsigned k0, unsigned k1, unsigned x0, unsigned x1,
    unsigned& o0, unsigned& o1)
{
    unsigned ks2 = k0 ^ k1 ^ 0x1BD11BDAu;
    unsigned ks[3] = {k0, k1, ks2};
    x0 += k0; x1 += k1;
    const int RA[4] = {13, 15, 26, 6};
    const int RB[4] = {17, 29, 16, 24};
#pragma unroll
    for (int r = 0; r < 5; ++r) {
        const int* R = (r & 1) ? RB : RA;
#pragma unroll
        for (int j = 0; j < 4; ++j) {
            x0 += x1; x1 = rotl32_(x1, R[j]); x1 ^= x0;
        }
        x0 += ks[(r + 1) % 3];
        x1 += ks[(r + 2) % 3] + (unsigned)(r + 1);
    }
    o0 = x0; o1 = x1;
}
__device__ __forceinline__ float dropout_val(
    float v, unsigned i, unsigned k0, unsigned k1)
{
    unsigned o0, o1;
    threefry2x32_(k0, k1, 0u, i, o0, o1);
    unsigned bits = o0 ^ o1;
    float u = __uint_as_float((bits >> 9) | 0x3f800000u) - 1.0f;
    return (u < 0.8f) ? (v * 1.25f) : 0.0f;
}

// ---------------- PTX helpers (all plain sm_80-era ISA) --------------------
__device__ __forceinline__ uint32_t smem_u32(const void* p) {
    uint32_t a;
    asm("{ .reg .u64 t; cvta.to.shared.u64 t, %1; cvt.u32.u64 %0, t; }"
        : "=r"(a) : "l"(p));
    return a;
}
__device__ __forceinline__ void cp16(uint32_t s, const void* g) {
    asm volatile("cp.async.cg.shared.global [%0], [%1], 16;"
                 :: "r"(s), "l"(g));
}
__device__ __forceinline__ void cp_commit() {
    asm volatile("cp.async.commit_group;" ::: "memory");
}
template <int N>
__device__ __forceinline__ void cp_wait() {
    asm volatile("cp.async.wait_group %0;" :: "n"(N) : "memory");
}
__device__ __forceinline__ void ldmx4(uint32_t a, uint32_t& r0, uint32_t& r1,
                                      uint32_t& r2, uint32_t& r3) {
    asm volatile("ldmatrix.sync.aligned.m8n8.x4.shared.b16 {%0,%1,%2,%3}, [%4];"
                 : "=r"(r0), "=r"(r1), "=r"(r2), "=r"(r3) : "r"(a));
}
__device__ __forceinline__ void mma16816(float* c, const uint32_t* a,
                                         const uint32_t* b) {
    asm volatile(
        "mma.sync.aligned.m16n8k16.row.col.f32.f16.f16.f32 "
        "{%0,%1,%2,%3}, {%4,%5,%6,%7}, {%8,%9}, {%0,%1,%2,%3};"
        : "+f"(c[0]), "+f"(c[1]), "+f"(c[2]), "+f"(c[3])
        : "r"(a[0]), "r"(a[1]), "r"(a[2]), "r"(a[3]), "r"(b[0]), "r"(b[1]));
}

// ---------------------------------------------------------------------------
// Prep: hs = x + 0.002*noise (fp32 + fp16); out init (route==2); recon=0
// ---------------------------------------------------------------------------
__global__ void prep_kernel(const float* __restrict__ x,
                            const float* __restrict__ noise,
                            const int*   __restrict__ route,
                            float* __restrict__ out,
                            float* __restrict__ recon)
{
    unsigned i4 = blockIdx.x * blockDim.x + threadIdx.x;
    unsigned base = i4 * 4u;
    if (base < (unsigned)NTOT) {
        float4 xv = *(const float4*)(x + base);
        float4 nv = *(const float4*)(noise + base);
        float4 h;
        h.x = xv.x + 0.002f * nv.x;
        h.y = xv.y + 0.002f * nv.y;
        h.z = xv.z + 0.002f * nv.z;
        h.w = xv.w + 0.002f * nv.w;
        *(float4*)(g_hs + base) = h;
        __half hv[4];
        hv[0] = __float2half(h.x); hv[1] = __float2half(h.y);
        hv[2] = __float2half(h.z); hv[3] = __float2half(h.w);
        *(uint2*)(g_hs16 + base) = *(uint2*)hv;
        int s = (int)((base >> 10) & 2047u);
        float4 o = (route[s] == 2) ? h : make_float4(0.f, 0.f, 0.f, 0.f);
        *(float4*)(out + base) = o;
    }
    if (i4 == 0) *recon = 0.0f;
}

// ---------------------------------------------------------------------------
// Fused weight prep: 12 matrices W[K,N] fp32 -> fp16 [N,K] (transposed)
// ---------------------------------------------------------------------------
struct WPrepArgs {
    const float* src[12];
    int K[12];
    int N[12];
    int pref[13];
};

__global__ void wprep_all(WPrepArgs a, __half* __restrict__ w16)
{
    int i = blockIdx.x * 256 + threadIdx.x;
    if (i >= a.pref[12]) return;
    int m = 0;
#pragma unroll
    for (int t = 0; t < 12; ++t)
        if (i >= a.pref[t + 1]) m = t + 1;
    int j = i - a.pref[m];
    int K = a.K[m], N = a.N[m];
    int n = j / K, k = j - n * K;
    w16[i] = __float2half(a.src[m][(size_t)k * N + n]);
}

// ---------------------------------------------------------------------------
// HMMA GEMM: tile 128x128, BK=64, 8 warps (4m x 2n), warp tile 32x64.
// Pure fp16 single-MMA. 3-stage cp.async pipeline (32KB/stage), one barrier
// per K-chunk of 64, early issue, swizzle c^(r&7) over 128B rows.
// __launch_bounds__(256, 2): 2 CTAs/SM (smem 2x96KB).
// ---------------------------------------------------------------------------
#define TILE_B    16384                // 128 rows x 128 bytes
#define ST_A      0
#define ST_B      (TILE_B)
#define STAGE_B   (2 * TILE_B)         // 32768
#define SMEM_BYTES (3 * STAGE_B)       // 98304

// 16B chunk c (0..7) of row r stored at chunk (c ^ (r & 7)); row pitch 128B
__device__ __forceinline__ uint32_t sw_off(int r, int c) {
    return (uint32_t)(r * 128) + (uint32_t)((c ^ (r & 7)) << 4);
}

__device__ __forceinline__ void issue_stage(
    uint32_t sb, const __half* A, const __half* B,
    int brow, int bcol, int K, int k0, int tid)
{
#pragma unroll
    for (int it = 0; it < 4; ++it) {
        int idx = it * 256 + tid;          // 0..1023
        int r = idx >> 3, c = idx & 7;
        uint32_t so = sw_off(r, c);
        size_t ga = (size_t)(brow + r) * K + k0 + c * 8;
        size_t gb = (size_t)(bcol + r) * K + k0 + c * 8;
        cp16(sb + ST_A + so, A + ga);
        cp16(sb + ST_B + so, B + gb);
    }
    cp_commit();
}

template <int EPI>
__global__ void __launch_bounds__(256, 2)
gemm_tc(const __half* __restrict__ A0, const __half* __restrict__ A1,
        const __half* __restrict__ B,
        const float* __restrict__ bias,
        __half* __restrict__ C,
        float* __restrict__ outC,
        int N, int K,
        const int* __restrict__ sub_choice, int expert, int branch_req,
        unsigned key0, unsigned key1,
        const float* __restrict__ hs, const int* __restrict__ route,
        float* __restrict__ recon_out, float recon_scale)
{
    if (branch_req >= 0 && sub_choice[expert] != branch_req) return;
    const __half* A = A0;
    if (EPI == 2 && sub_choice[expert] < 2) A = A1;

    extern __shared__ char smem[];
    uint32_t sbase = smem_u32(smem);

    const int tid = threadIdx.x;
    const int wid = tid >> 5, lane = tid & 31;
    const int wm = wid >> 1, wn = wid & 1;
    const int brow = blockIdx.y * 128, bcol = blockIdx.x * 128;

    float acc[2][8][4];
#pragma unroll
    for (int mi = 0; mi < 2; ++mi)
#pragma unroll
        for (int nj = 0; nj < 8; ++nj)
#pragma unroll
            for (int c = 0; c < 4; ++c) acc[mi][nj][c] = 0.f;

    // ldmatrix lane geometry: hoisted row byte-offsets + swizzle keys
    const int a_row = wm * 32 + (lane & 15);
    const int a_cb  = lane >> 4;                           // chunk +0/+1
    const int b_row = wn * 64 + (lane & 7) + ((lane >> 4) << 3);
    const int b_cb  = (lane >> 3) & 1;

    uint32_t a_ro[2], b_ro[4];
    int a_swk[2], b_swk[4];
#pragma unroll
    for (int mi = 0; mi < 2; ++mi) {
        int r = a_row + mi * 16;
        a_ro[mi] = (uint32_t)(r * 128);
        a_swk[mi] = r & 7;
    }
#pragma unroll
    for (int g = 0; g < 4; ++g) {
        int r = b_row + g * 16;
        b_ro[g] = (uint32_t)(r * 128);
        b_swk[g] = r & 7;
    }

    const int nch = K >> 6;              // >= 2 for all our shapes
    issue_stage(sbase,           A, B, brow, bcol, K, 0,  tid);
    issue_stage(sbase + STAGE_B, A, B, brow, bcol, K, 64, tid);

    int rs = 0, ws = 2;
    for (int kc = 0; kc < nch; ++kc) {
        if (kc + 1 < nch) cp_wait<1>(); else cp_wait<0>();
        __syncthreads();
        // slot ws == slot (kc-1)%3: finished by all warps at the barrier.
        if (kc + 2 < nch)
            issue_stage(sbase + (uint32_t)ws * STAGE_B,
                        A, B, brow, bcol, K, (kc + 2) << 6, tid);

        uint32_t st = sbase + (uint32_t)rs * STAGE_B;
#pragma unroll
        for (int kk = 0; kk < 4; ++kk) {
            uint32_t ah[2][4];
#pragma unroll
            for (int mi = 0; mi < 2; ++mi) {
                uint32_t ao = a_ro[mi] +
                    (uint32_t)((((kk * 2 + a_cb) ^ a_swk[mi])) << 4);
                ldmx4(st + ST_A + ao, ah[mi][0], ah[mi][1], ah[mi][2], ah[mi][3]);
            }
            // B-fragment double buffer: load g+1 while computing g
            uint32_t bh[2][4];
            {
                uint32_t bo = b_ro[0] +
                    (uint32_t)((((kk * 2 + b_cb) ^ b_swk[0])) << 4);
                ldmx4(st + ST_B + bo, bh[0][0], bh[0][1], bh[0][2], bh[0][3]);
            }
#pragma unroll
            for (int g = 0; g < 4; ++g) {
                const int cur = g & 1, nxt = cur ^ 1;
                if (g < 3) {
                    uint32_t bo = b_ro[g + 1] +
                        (uint32_t)((((kk * 2 + b_cb) ^ b_swk[g + 1])) << 4);
                    ldmx4(st + ST_B + bo,
                          bh[nxt][0], bh[nxt][1], bh[nxt][2], bh[nxt][3]);
                }
#pragma unroll
                for (int p = 0; p < 2; ++p)
#pragma unroll
                    for (int mi = 0; mi < 2; ++mi)
                        mma16816(acc[mi][g * 2 + p], ah[mi], &bh[cur][p * 2]);
            }
        }
        rs = (rs == 2) ? 0 : rs + 1;
        ws = (ws == 2) ? 0 : ws + 1;
    }

    // ----------------- epilogue -----------------
    const int lane4 = lane >> 2;
    const int lanec = (lane & 3) * 2;
    float lsum = 0.f;

#pragma unroll
    for (int mi = 0; mi < 2; ++mi) {
        int r0g = brow + wm * 32 + mi * 16 + lane4;
        int r1g = r0g + 8;
        int rt0 = 0, rt1 = 0;
        if (EPI == 2) {
            rt0 = route[r0g & 2047];
            rt1 = route[r1g & 2047];
        }
#pragma unroll
        for (int nj = 0; nj < 8; ++nj) {
            int col = bcol + wn * 64 + nj * 8 + lanec;
            float b0 = bias[col], b1 = bias[col + 1];
            float v00 = acc[mi][nj][0] + b0, v01 = acc[mi][nj][1] + b1;
            float v10 = acc[mi][nj][2] + b0, v11 = acc[mi][nj][3] + b1;
            unsigned i0 = (unsigned)r0g * (unsigned)N + (unsigned)col;
            unsigned i1 = (unsigned)r1g * (unsigned)N + (unsigned)col;

            if (EPI == 0 || EPI == 1) {
                v00 = tanhf(v00); v01 = tanhf(v01);
                v10 = tanhf(v10); v11 = tanhf(v11);
                if (EPI == 0) {
                    v00 = dropout_val(v00, i0, key0, key1);
                    v01 = dropout_val(v01, i0 + 1, key0, key1);
                    v10 = dropout_val(v10, i1, key0, key1);
                    v11 = dropout_val(v11, i1 + 1, key0, key1);
                }
                __half2 p0, p1;
                p0.x = __float2half(v00); p0.y = __float2half(v01);
                p1.x = __float2half(v10); p1.y = __float2half(v11);
                *(__half2*)(C + i0) = p0;
                *(__half2*)(C + i1) = p1;
            } else {
                float d;
                d = hs[i0] - v00;     lsum += d * d;
                d = hs[i0 + 1] - v01; lsum += d * d;
                d = hs[i1] - v10;     lsum += d * d;
                d = hs[i1 + 1] - v11; lsum += d * d;
                if (rt0 == expert) {
                    outC[i0] = v00; outC[i0 + 1] = v01;
                }
                if (rt1 == expert) {
                    outC[i1] = v10; outC[i1 + 1] = v11;
                }
            }
        }
    }

    if (EPI == 2) {
#pragma unroll
        for (int s = 16; s > 0; s >>= 1)
            lsum += __shfl_xor_sync(0xFFFFFFFFu, lsum, s);
        if (lane == 0) atomicAdd(recon_out, lsum * recon_scale);
    }
}

// ---------------------------------------------------------------------------
// Host side: prep+wprep on default stream, FORK -> expert0 on default,
// expert1 on secondary stream -> JOIN.
// ---------------------------------------------------------------------------
extern "C" void kernel_launch(void* const* d_in, const int* in_sizes, int n_in,
                              void* d_out, int out_size)
{
    const float* x          = (const float*)d_in[0];
    const float* noise      = (const float*)d_in[1];
    const int*   route      = (const int*)  d_in[2];
    const int*   sub_choice = (const int*)  d_in[3];

    float* out   = (float*)d_out;
    float* recon = out + (out_size - 1);

    float* p_hs;
    __half *p_hs16, *p_h16, *p_t16, *p_s16, *p_w16;
    cudaGetSymbolAddress((void**)&p_hs,   g_hs);
    cudaGetSymbolAddress((void**)&p_hs16, g_hs16);
    cudaGetSymbolAddress((void**)&p_h16,  g_h16);
    cudaGetSymbolAddress((void**)&p_t16,  g_t16);
    cudaGetSymbolAddress((void**)&p_s16,  g_s16);
    cudaGetSymbolAddress((void**)&p_w16,  g_w16);

    static cudaStream_t s1 = nullptr;
    static cudaEvent_t ev_fork = nullptr, ev_join = nullptr;
    if (s1 == nullptr) {
        cudaStreamCreateWithFlags(&s1, cudaStreamNonBlocking);
        cudaEventCreateWithFlags(&ev_fork, cudaEventDisableTiming);
        cudaEventCreateWithFlags(&ev_join, cudaEventDisableTiming);
        cudaFuncSetAttribute(gemm_tc<0>, cudaFuncAttributeMaxDynamicSharedMemorySize, SMEM_BYTES);
        cudaFuncSetAttribute(gemm_tc<1>, cudaFuncAttributeMaxDynamicSharedMemorySize, SMEM_BYTES);
        cudaFuncSetAttribute(gemm_tc<2>, cudaFuncAttributeMaxDynamicSharedMemorySize, SMEM_BYTES);
    }

    // --- exact JAX partitionable key derivation (verified R5) ---
    unsigned ek[2][2];
    threefry2x32_(0u, 42u, 0u, 0u, ek[0][0], ek[0][1]);
    threefry2x32_(0u, 42u, 0u, 1u, ek[1][0], ek[1][1]);
    unsigned kk1[2][2], kk2[2][2], kk3[2][2];
    for (int e = 0; e < 2; ++e) {
        threefry2x32_(ek[e][0], ek[e][1], 0u, 0u, kk1[e][0], kk1[e][1]);
        threefry2x32_(ek[e][0], ek[e][1], 0u, 1u, kk2[e][0], kk2[e][1]);
        threefry2x32_(ek[e][0], ek[e][1], 0u, 2u, kk3[e][0], kk3[e][1]);
    }

    prep_kernel<<<NTOT / 4 / 256, 256>>>(x, noise, route, out, recon);

    // --- fused weight prep: 12 matrices, one launch ---
    long woff[2][6];
    WPrepArgs wa;
    {
        int off = 0, m = 0;
        for (int e = 0; e < 2; ++e) {
            int base = 4 + e * 12;
            int d = (e == 0) ? 512 : 256, dh = d / 2;
            const float* srcs[6] = {
                (const float*)d_in[base + 0],
                (const float*)d_in[base + 2],
                (const float*)d_in[base + 4],
                (const float*)d_in[base + 6],
                (const float*)d_in[base + 8],
                (const float*)d_in[base + 10],
            };
            int Ks[6] = {HDIM, d, dh, d, dh, d};
            int Ns[6] = {d, dh, d, dh, d, HDIM};
            for (int wi = 0; wi < 6; ++wi, ++m) {
                woff[e][wi] = off;
                wa.src[m] = srcs[wi];
                wa.K[m] = Ks[wi];
                wa.N[m] = Ns[wi];
                wa.pref[m] = off;
                off += Ks[wi] * Ns[wi];
            }
        }
        wa.pref[12] = off;
        wprep_all<<<(off + 255) / 256, 256>>>(wa, p_w16);
    }

    // FORK
    cudaEventRecord(ev_fork, 0);
    cudaStreamWaitEvent(s1, ev_fork, 0);

    const float recon_scale = 1.0f / (2.0f * (float)NTOT);

    for (int e = 0; e < 2; ++e) {
        int base = 4 + e * 12;
        const float* db   = (const float*)d_in[base + 1];
        const float* s0db = (const float*)d_in[base + 3];
        const float* s0ub = (const float*)d_in[base + 5];
        const float* s1db = (const float*)d_in[base + 7];
        const float* s1ub = (const float*)d_in[base + 9];
        const float* ub   = (const float*)d_in[base + 11];
        int d = (e == 0) ? 512 : 256, dh = d / 2;
        cudaStream_t st = (e == 0) ? (cudaStream_t)0 : s1;

        __half* h16  = p_h16 + (size_t)e * TOK * 512;
        __half* t16  = p_t16 + (size_t)e * TOK * 256;
        __half* sv16 = p_s16 + (size_t)e * TOK * 512;

        // GEMM1: hs @ dw -> tanh -> dropout -> h
        gemm_tc<0><<<dim3(d / 128, TOK / 128), 256, SMEM_BYTES, st>>>(
            p_hs16, nullptr, p_w16 + woff[e][0], db,
            h16, nullptr,
            d, HDIM, sub_choice, e, -1, kk1[e][0], kk1[e][1],
            nullptr, nullptr, nullptr, 0.f);

        // s0 branch
        gemm_tc<0><<<dim3(dh / 128, TOK / 128), 256, SMEM_BYTES, st>>>(
            h16, nullptr, p_w16 + woff[e][1], s0db,
            t16, nullptr,
            dh, d, sub_choice, e, 0, kk2[e][0], kk2[e][1],
            nullptr, nullptr, nullptr, 0.f);
        gemm_tc<1><<<dim3(d / 128, TOK / 128), 256, SMEM_BYTES, st>>>(
            t16, nullptr, p_w16 + woff[e][2], s0ub,
            sv16, nullptr,
            d, dh, sub_choice, e, 0, 0u, 0u,
            nullptr, nullptr, nullptr, 0.f);

        // s1 branch
        gemm_tc<0><<<dim3(dh / 128, TOK / 128), 256, SMEM_BYTES, st>>>(
            h16, nullptr, p_w16 + woff[e][3], s1db,
            t16, nullptr,
            dh, d, sub_choice, e, 1, kk3[e][0], kk3[e][1],
            nullptr, nullptr, nullptr, 0.f);
        gemm_tc<1><<<dim3(d / 128, TOK / 128), 256, SMEM_BYTES, st>>>(
            t16, nullptr, p_w16 + woff[e][4], s1ub,
            sv16, nullptr,
            d, dh, sub_choice, e, 1, 0u, 0u,
            nullptr, nullptr, nullptr, 0.f);

        // GEMM3: (choice<2 ? s : h) @ uw -> route-select out + recon
        gemm_tc<2><<<dim3(HDIM / 128, TOK / 128), 256, SMEM_BYTES, st>>>(
            h16, sv16, p_w16 + woff[e][5], ub,
            nullptr, out,
            HDIM, d, sub_choice, e, -1, 0u, 0u,
            p_hs, route, recon, recon_scale);
    }

    // JOIN
    cudaEventRecord(ev_join, s1);
    cudaStreamWaitEvent(0, ev_join, 0);
}

// round 16
// speedup vs baseline: 2.8760x; 1.1051x over previous
#include <cuda_runtime.h>
#include <cuda_fp16.h>
#include <cstdint>

// ---------------------------------------------------------------------------
// Problem: x (8,2048,1024) -> 16384 tokens x 1024. Expert0 d=512, Expert1 d=256.
// Output: opt (16384*1024 fp32) + recon scalar.
// R16: software-pipelined fragment prefetch in the HMMA mainloop (B one step
// ahead, A double-buffered across kk); fp32 hs eliminated (prep writes hs16 +
// predicated route==2 passthrough; recon uses hs16). Pure fp16 single-MMA,
// BK=64, 3-stage cp.async, 2 CTAs/SM, expert chains on parallel streams.
// ---------------------------------------------------------------------------
#define TOK   16384
#define HDIM  1024
#define NTOT  (TOK * HDIM)

// ---------------- static scratch (no allocs allowed) -----------------------
__device__ __half  g_hs16[NTOT];
__device__ __half  g_h16[2 * TOK * 512];
__device__ __half  g_t16[2 * TOK * 256];
__device__ __half  g_s16[2 * TOK * 512];
#define WTOT 2228224
__device__ __half  g_w16[WTOT];

// ---------------- threefry (exact JAX partitionable PRNG, verified R5) -----
__host__ __device__ __forceinline__ unsigned rotl32_(unsigned x, int r) {
    return (x << r) | (x >> (32 - r));
}
__host__ __device__ __forceinline__ void threefry2x32_(
    unsigned k0, unsigned k1, unsigned x0, unsigned x1,
    unsigned& o0, unsigned& o1)
{
    unsigned ks2 = k0 ^ k1 ^ 0x1BD11BDAu;
    unsigned ks[3] = {k0, k1, ks2};
    x0 += k0; x1 += k1;
    const int RA[4] = {13, 15, 26, 6};
    const int RB[4] = {17, 29, 16, 24};
#pragma unroll
    for (int r = 0; r < 5; ++r) {
        const int* R = (r & 1) ? RB : RA;
#pragma unroll
        for (int j = 0; j < 4; ++j) {
            x0 += x1; x1 = rotl32_(x1, R[j]); x1 ^= x0;
        }
        x0 += ks[(r + 1) % 3];
        x1 += ks[(r + 2) % 3] + (unsigned)(r + 1);
    }
    o0 = x0; o1 = x1;
}
__device__ __forceinline__ float dropout_val(
    float v, unsigned i, unsigned k0, unsigned k1)
{
    unsigned o0, o1;
    threefry2x32_(k0, k1, 0u, i, o0, o1);
    unsigned bits = o0 ^ o1;
    float u = __uint_as_float((bits >> 9) | 0x3f800000u) - 1.0f;
    return (u < 0.8f) ? (v * 1.25f) : 0.0f;
}

// ---------------- PTX helpers (all plain sm_80-era ISA) --------------------
__device__ __forceinline__ uint32_t smem_u32(const void* p) {
    uint32_t a;
    asm("{ .reg .u64 t; cvta.to.shared.u64 t, %1; cvt.u32.u64 %0, t; }"
        : "=r"(a) : "l"(p));
    return a;
}
__device__ __forceinline__ void cp16(uint32_t s, const void* g) {
    asm volatile("cp.async.cg.shared.global [%0], [%1], 16;"
                 :: "r"(s), "l"(g));
}
__device__ __forceinline__ void cp_commit() {
    asm volatile("cp.async.commit_group;" ::: "memory");
}
template <int N>
__device__ __forceinline__ void cp_wait() {
    asm volatile("cp.async.wait_group %0;" :: "n"(N) : "memory");
}
__device__ __forceinline__ void ldmx4(uint32_t a, uint32_t& r0, uint32_t& r1,
                                      uint32_t& r2, uint32_t& r3) {
    asm volatile("ldmatrix.sync.aligned.m8n8.x4.shared.b16 {%0,%1,%2,%3}, [%4];"
                 : "=r"(r0), "=r"(r1), "=r"(r2), "=r"(r3) : "r"(a));
}
__device__ __forceinline__ void mma16816(float* c, const uint32_t* a,
                                         const uint32_t* b) {
    asm volatile(
        "mma.sync.aligned.m16n8k16.row.col.f32.f16.f16.f32 "
        "{%0,%1,%2,%3}, {%4,%5,%6,%7}, {%8,%9}, {%0,%1,%2,%3};"
        : "+f"(c[0]), "+f"(c[1]), "+f"(c[2]), "+f"(c[3])
        : "r"(a[0]), "r"(a[1]), "r"(a[2]), "r"(a[3]), "r"(b[0]), "r"(b[1]));
}

// ---------------------------------------------------------------------------
// Prep: hs = x + 0.002*noise -> hs16; out passthrough ONLY where route==2
// (other rows are written by exactly one GEMM3); recon slot zeroed.
// ---------------------------------------------------------------------------
__global__ void prep_kernel(const float* __restrict__ x,
                            const float* __restrict__ noise,
                            const int*   __restrict__ route,
                            float* __restrict__ out,
                            float* __restrict__ recon)
{
    unsigned i4 = blockIdx.x * blockDim.x + threadIdx.x;
    unsigned base = i4 * 4u;
    if (base < (unsigned)NTOT) {
        float4 xv = *(const float4*)(x + base);
        float4 nv = *(const float4*)(noise + base);
        float4 h;
        h.x = xv.x + 0.002f * nv.x;
        h.y = xv.y + 0.002f * nv.y;
        h.z = xv.z + 0.002f * nv.z;
        h.w = xv.w + 0.002f * nv.w;
        __half hv[4];
        hv[0] = __float2half(h.x); hv[1] = __float2half(h.y);
        hv[2] = __float2half(h.z); hv[3] = __float2half(h.w);
        *(uint2*)(g_hs16 + base) = *(uint2*)hv;
        int s = (int)((base >> 10) & 2047u);
        if (route[s] == 2) *(float4*)(out + base) = h;
    }
    if (i4 == 0) *recon = 0.0f;
}

// ---------------------------------------------------------------------------
// Fused weight prep: 12 matrices W[K,N] fp32 -> fp16 [N,K] (transposed)
// ---------------------------------------------------------------------------
struct WPrepArgs {
    const float* src[12];
    int K[12];
    int N[12];
    int pref[13];
};

__global__ void wprep_all(WPrepArgs a, __half* __restrict__ w16)
{
    int i = blockIdx.x * 256 + threadIdx.x;
    if (i >= a.pref[12]) return;
    int m = 0;
#pragma unroll
    for (int t = 0; t < 12; ++t)
        if (i >= a.pref[t + 1]) m = t + 1;
    int j = i - a.pref[m];
    int K = a.K[m], N = a.N[m];
    int n = j / K, k = j - n * K;
    w16[i] = __float2half(a.src[m][(size_t)k * N + n]);
}

// ---------------------------------------------------------------------------
// HMMA GEMM: tile 128x128, BK=64, 8 warps (4m x 2n), warp tile 32x64.
// Pure fp16 single-MMA, fully software-pipelined fragments:
// flattened (kk,g) steps with B prefetched one step ahead and A
// double-buffered across kk. 3-stage cp.async, one barrier per chunk.
// __launch_bounds__(256, 2): 2 CTAs/SM (smem 2x96KB).
// ---------------------------------------------------------------------------
#define TILE_B    16384                // 128 rows x 128 bytes
#define ST_A      0
#define ST_B      (TILE_B)
#define STAGE_B   (2 * TILE_B)         // 32768
#define SMEM_BYTES (3 * STAGE_B)       // 98304

// 16B chunk c (0..7) of row r stored at chunk (c ^ (r & 7)); row pitch 128B
__device__ __forceinline__ uint32_t sw_off(int r, int c) {
    return (uint32_t)(r * 128) + (uint32_t)((c ^ (r & 7)) << 4);
}

__device__ __forceinline__ void issue_stage(
    uint32_t sb, const __half* A, const __half* B,
    int brow, int bcol, int K, int k0, int tid)
{
#pragma unroll
    for (int it = 0; it < 4; ++it) {
        int idx = it * 256 + tid;          // 0..1023
        int r = idx >> 3, c = idx & 7;
        uint32_t so = sw_off(r, c);
        size_t ga = (size_t)(brow + r) * K + k0 + c * 8;
        size_t gb = (size_t)(bcol + r) * K + k0 + c * 8;
        cp16(sb + ST_A + so, A + ga);
        cp16(sb + ST_B + so, B + gb);
    }
    cp_commit();
}

template <int EPI>
__global__ void __launch_bounds__(256, 2)
gemm_tc(const __half* __restrict__ A0, const __half* __restrict__ A1,
        const __half* __restrict__ B,
        const float* __restrict__ bias,
        __half* __restrict__ C,
        float* __restrict__ outC,
        int N, int K,
        const int* __restrict__ sub_choice, int expert, int branch_req,
        unsigned key0, unsigned key1,
        const __half* __restrict__ hs16, const int* __restrict__ route,
        float* __restrict__ recon_out, float recon_scale)
{
    if (branch_req >= 0 && sub_choice[expert] != branch_req) return;
    const __half* A = A0;
    if (EPI == 2 && sub_choice[expert] < 2) A = A1;

    extern __shared__ char smem[];
    uint32_t sbase = smem_u32(smem);

    const int tid = threadIdx.x;
    const int wid = tid >> 5, lane = tid & 31;
    const int wm = wid >> 1, wn = wid & 1;
    const int brow = blockIdx.y * 128, bcol = blockIdx.x * 128;

    float acc[2][8][4];
#pragma unroll
    for (int mi = 0; mi < 2; ++mi)
#pragma unroll
        for (int nj = 0; nj < 8; ++nj)
#pragma unroll
            for (int c = 0; c < 4; ++c) acc[mi][nj][c] = 0.f;

    // ldmatrix lane geometry: hoisted row byte-offsets + swizzle keys
    const int a_row = wm * 32 + (lane & 15);
    const int a_cb  = lane >> 4;
    const int b_row = wn * 64 + (lane & 7) + ((lane >> 4) << 3);
    const int b_cb  = (lane >> 3) & 1;

    uint32_t a_ro[2], b_ro[4];
    int a_swk[2], b_swk[4];
#pragma unroll
    for (int mi = 0; mi < 2; ++mi) {
        int r = a_row + mi * 16;
        a_ro[mi] = (uint32_t)(r * 128);
        a_swk[mi] = r & 7;
    }
#pragma unroll
    for (int g = 0; g < 4; ++g) {
        int r = b_row + g * 16;
        b_ro[g] = (uint32_t)(r * 128);
        b_swk[g] = r & 7;
    }

    const int nch = K >> 6;
    issue_stage(sbase,           A, B, brow, bcol, K, 0,  tid);
    issue_stage(sbase + STAGE_B, A, B, brow, bcol, K, 64, tid);

    int rs = 0, ws = 2;
    for (int kc = 0; kc < nch; ++kc) {
        if (kc + 1 < nch) cp_wait<1>(); else cp_wait<0>();
        __syncthreads();
        // slot ws == slot (kc-1)%3: finished by all warps at the barrier.
        if (kc + 2 < nch)
            issue_stage(sbase + (uint32_t)ws * STAGE_B,
                        A, B, brow, bcol, K, (kc + 2) << 6, tid);

        uint32_t st = sbase + (uint32_t)rs * STAGE_B;

        // fragment buffers: A double-buffered by kk parity, B by step parity
        uint32_t ah[2][2][4];
        uint32_t bh[2][4];

        // prologue: A(kk=0), B(kk=0,g=0)
#pragma unroll
        for (int mi = 0; mi < 2; ++mi) {
            uint32_t ao = a_ro[mi] + (uint32_t)(((a_cb ^ a_swk[mi])) << 4);
            ldmx4(st + ST_A + ao,
                  ah[0][mi][0], ah[0][mi][1], ah[0][mi][2], ah[0][mi][3]);
        }
        {
            uint32_t bo = b_ro[0] + (uint32_t)(((b_cb ^ b_swk[0])) << 4);
            ldmx4(st + ST_B + bo, bh[0][0], bh[0][1], bh[0][2], bh[0][3]);
        }

#pragma unroll
        for (int s = 0; s < 16; ++s) {
            const int kk = s >> 2, g = s & 3;
            const int cur = s & 1, nxt = cur ^ 1;
            // prefetch step s+1 fragments
            if (s < 15) {
                const int s2 = s + 1, kk2 = s2 >> 2, g2 = s2 & 3;
                if (g2 == 0) {
#pragma unroll
                    for (int mi = 0; mi < 2; ++mi) {
                        uint32_t ao = a_ro[mi] +
                            (uint32_t)((((kk2 * 2 + a_cb) ^ a_swk[mi])) << 4);
                        ldmx4(st + ST_A + ao,
                              ah[kk2 & 1][mi][0], ah[kk2 & 1][mi][1],
                              ah[kk2 & 1][mi][2], ah[kk2 & 1][mi][3]);
                    }
                }
                uint32_t bo = b_ro[g2] +
                    (uint32_t)((((kk2 * 2 + b_cb) ^ b_swk[g2])) << 4);
                ldmx4(st + ST_B + bo,
                      bh[nxt][0], bh[nxt][1], bh[nxt][2], bh[nxt][3]);
            }
            // 4 MMAs for step (kk, g)
#pragma unroll
            for (int p = 0; p < 2; ++p)
#pragma unroll
                for (int mi = 0; mi < 2; ++mi)
                    mma16816(acc[mi][g * 2 + p], ah[kk & 1][mi], &bh[cur][p * 2]);
        }
        rs = (rs == 2) ? 0 : rs + 1;
        ws = (ws == 2) ? 0 : ws + 1;
    }

    // ----------------- epilogue -----------------
    const int lane4 = lane >> 2;
    const int lanec = (lane & 3) * 2;
    float lsum = 0.f;

#pragma unroll
    for (int mi = 0; mi < 2; ++mi) {
        int r0g = brow + wm * 32 + mi * 16 + lane4;
        int r1g = r0g + 8;
        int rt0 = 0, rt1 = 0;
        if (EPI == 2) {
            rt0 = route[r0g & 2047];
            rt1 = route[r1g & 2047];
        }
#pragma unroll
        for (int nj = 0; nj < 8; ++nj) {
            int col = bcol + wn * 64 + nj * 8 + lanec;
            float b0 = bias[col], b1 = bias[col + 1];
            float v00 = acc[mi][nj][0] + b0, v01 = acc[mi][nj][1] + b1;
            float v10 = acc[mi][nj][2] + b0, v11 = acc[mi][nj][3] + b1;
            unsigned i0 = (unsigned)r0g * (unsigned)N + (unsigned)col;
            unsigned i1 = (unsigned)r1g * (unsigned)N + (unsigned)col;

            if (EPI == 0 || EPI == 1) {
                v00 = tanhf(v00); v01 = tanhf(v01);
                v10 = tanhf(v10); v11 = tanhf(v11);
                if (EPI == 0) {
                    v00 = dropout_val(v00, i0, key0, key1);
                    v01 = dropout_val(v01, i0 + 1, key0, key1);
                    v10 = dropout_val(v10, i1, key0, key1);
                    v11 = dropout_val(v11, i1 + 1, key0, key1);
                }
                __half2 p0, p1;
                p0.x = __float2half(v00); p0.y = __float2half(v01);
                p1.x = __float2half(v10); p1.y = __float2half(v11);
                *(__half2*)(C + i0) = p0;
                *(__half2*)(C + i1) = p1;
            } else {
                __half2 h0 = *(const __half2*)(hs16 + i0);
                __half2 h1 = *(const __half2*)(hs16 + i1);
                float d;
                d = __half2float(h0.x) - v00; lsum += d * d;
                d = __half2float(h0.y) - v01; lsum += d * d;
                d = __half2float(h1.x) - v10; lsum += d * d;
                d = __half2float(h1.y) - v11; lsum += d * d;
                if (rt0 == expert) {
                    outC[i0] = v00; outC[i0 + 1] = v01;
                }
                if (rt1 == expert) {
                    outC[i1] = v10; outC[i1 + 1] = v11;
                }
            }
        }
    }

    if (EPI == 2) {
#pragma unroll
        for (int s = 16; s > 0; s >>= 1)
            lsum += __shfl_xor_sync(0xFFFFFFFFu, lsum, s);
        if (lane == 0) atomicAdd(recon_out, lsum * recon_scale);
    }
}

// ---------------------------------------------------------------------------
// Host side: prep+wprep on default stream, FORK -> expert0 on default,
// expert1 on secondary stream -> JOIN.
// ---------------------------------------------------------------------------
extern "C" void kernel_launch(void* const* d_in, const int* in_sizes, int n_in,
                              void* d_out, int out_size)
{
    const float* x          = (const float*)d_in[0];
    const float* noise      = (const float*)d_in[1];
    const int*   route      = (const int*)  d_in[2];
    const int*   sub_choice = (const int*)  d_in[3];

    float* out   = (float*)d_out;
    float* recon = out + (out_size - 1);

    __half *p_hs16, *p_h16, *p_t16, *p_s16, *p_w16;
    cudaGetSymbolAddress((void**)&p_hs16, g_hs16);
    cudaGetSymbolAddress((void**)&p_h16,  g_h16);
    cudaGetSymbolAddress((void**)&p_t16,  g_t16);
    cudaGetSymbolAddress((void**)&p_s16,  g_s16);
    cudaGetSymbolAddress((void**)&p_w16,  g_w16);

    static cudaStream_t s1 = nullptr;
    static cudaEvent_t ev_fork = nullptr, ev_join = nullptr;
    if (s1 == nullptr) {
        cudaStreamCreateWithFlags(&s1, cudaStreamNonBlocking);
        cudaEventCreateWithFlags(&ev_fork, cudaEventDisableTiming);
        cudaEventCreateWithFlags(&ev_join, cudaEventDisableTiming);
        cudaFuncSetAttribute(gemm_tc<0>, cudaFuncAttributeMaxDynamicSharedMemorySize, SMEM_BYTES);
        cudaFuncSetAttribute(gemm_tc<1>, cudaFuncAttributeMaxDynamicSharedMemorySize, SMEM_BYTES);
        cudaFuncSetAttribute(gemm_tc<2>, cudaFuncAttributeMaxDynamicSharedMemorySize, SMEM_BYTES);
    }

    // --- exact JAX partitionable key derivation (verified R5) ---
    unsigned ek[2][2];
    threefry2x32_(0u, 42u, 0u, 0u, ek[0][0], ek[0][1]);
    threefry2x32_(0u, 42u, 0u, 1u, ek[1][0], ek[1][1]);
    unsigned kk1[2][2], kk2[2][2], kk3[2][2];
    for (int e = 0; e < 2; ++e) {
        threefry2x32_(ek[e][0], ek[e][1], 0u, 0u, kk1[e][0], kk1[e][1]);
        threefry2x32_(ek[e][0], ek[e][1], 0u, 1u, kk2[e][0], kk2[e][1]);
        threefry2x32_(ek[e][0], ek[e][1], 0u, 2u, kk3[e][0], kk3[e][1]);
    }

    prep_kernel<<<NTOT / 4 / 256, 256>>>(x, noise, route, out, recon);

    // --- fused weight prep: 12 matrices, one launch ---
    long woff[2][6];
    WPrepArgs wa;
    {
        int off = 0, m = 0;
        for (int e = 0; e < 2; ++e) {
            int base = 4 + e * 12;
            int d = (e == 0) ? 512 : 256, dh = d / 2;
            const float* srcs[6] = {
                (const float*)d_in[base + 0],
                (const float*)d_in[base + 2],
                (const float*)d_in[base + 4],
                (const float*)d_in[base + 6],
                (const float*)d_in[base + 8],
                (const float*)d_in[base + 10],
            };
            int Ks[6] = {HDIM, d, dh, d, dh, d};
            int Ns[6] = {d, dh, d, dh, d, HDIM};
            for (int wi = 0; wi < 6; ++wi, ++m) {
                woff[e][wi] = off;
                wa.src[m] = srcs[wi];
                wa.K[m] = Ks[wi];
                wa.N[m] = Ns[wi];
                wa.pref[m] = off;
                off += Ks[wi] * Ns[wi];
            }
        }
        wa.pref[12] = off;
        wprep_all<<<(off + 255) / 256, 256>>>(wa, p_w16);
    }

    // FORK
    cudaEventRecord(ev_fork, 0);
    cudaStreamWaitEvent(s1, ev_fork, 0);

    const float recon_scale = 1.0f / (2.0f * (float)NTOT);

    for (int e = 0; e < 2; ++e) {
        int base = 4 + e * 12;
        const float* db   = (const float*)d_in[base + 1];
        const float* s0db = (const float*)d_in[base + 3];
        const float* s0ub = (const float*)d_in[base + 5];
        const float* s1db = (const float*)d_in[base + 7];
        const float* s1ub = (const float*)d_in[base + 9];
        const float* ub   = (const float*)d_in[base + 11];
        int d = (e == 0) ? 512 : 256, dh = d / 2;
        cudaStream_t st = (e == 0) ? (cudaStream_t)0 : s1;

        __half* h16  = p_h16 + (size_t)e * TOK * 512;
        __half* t16  = p_t16 + (size_t)e * TOK * 256;
        __half* sv16 = p_s16 + (size_t)e * TOK * 512;

        // GEMM1: hs @ dw -> tanh -> dropout -> h
        gemm_tc<0><<<dim3(d / 128, TOK / 128), 256, SMEM_BYTES, st>>>(
            p_hs16, nullptr, p_w16 + woff[e][0], db,
            h16, nullptr,
            d, HDIM, sub_choice, e, -1, kk1[e][0], kk1[e][1],
            nullptr, nullptr, nullptr, 0.f);

        // s0 branch
        gemm_tc<0><<<dim3(dh / 128, TOK / 128), 256, SMEM_BYTES, st>>>(
            h16, nullptr, p_w16 + woff[e][1], s0db,
            t16, nullptr,
            dh, d, sub_choice, e, 0, kk2[e][0], kk2[e][1],
            nullptr, nullptr, nullptr, 0.f);
        gemm_tc<1><<<dim3(d / 128, TOK / 128), 256, SMEM_BYTES, st>>>(
            t16, nullptr, p_w16 + woff[e][2], s0ub,
            sv16, nullptr,
            d, dh, sub_choice, e, 0, 0u, 0u,
            nullptr, nullptr, nullptr, 0.f);

        // s1 branch
        gemm_tc<0><<<dim3(dh / 128, TOK / 128), 256, SMEM_BYTES, st>>>(
            h16, nullptr, p_w16 + woff[e][3], s1db,
            t16, nullptr,
            dh, d, sub_choice, e, 1, kk3[e][0], kk3[e][1],
            nullptr, nullptr, nullptr, 0.f);
        gemm_tc<1><<<dim3(d / 128, TOK / 128), 256, SMEM_BYTES, st>>>(
            t16, nullptr, p_w16 + woff[e][4], s1ub,
            sv16, nullptr,
            d, dh, sub_choice, e, 1, 0u, 0u,
            nullptr, nullptr, nullptr, 0.f);

        // GEMM3: (choice<2 ? s : h) @ uw -> route-select out + recon
        gemm_tc<2><<<dim3(HDIM / 128, TOK / 128), 256, SMEM_BYTES, st>>>(
            h16, sv16, p_w16 + woff[e][5], ub,
            nullptr, out,
            HDIM, d, sub_choice, e, -1, 0u, 0u,
            p_hs16, route, recon, recon_scale);
    }

    // JOIN
    cudaEventRecord(ev_join, s1);
    cudaStreamWaitEvent(0, ev_join, 0);
}